// round 3
// baseline (speedup 1.0000x reference)
#include <cuda_runtime.h>
#include <math.h>

// Problem shapes (fixed): B=2, T=1024, D=1024, N=8, HD=128, K=32
// Inputs (metadata order):
//  0 x         [2,1024,1024] f32
//  1 enc_q     [8,1024,128]  f32
//  2 enc_v     [8,1024,128]  f32
//  3 decoder   [1024,1024]   f32
//  4 hebbian   [8,128,128]   f32
//  5 m_w1      [1024,512]    f32
//  6 m_b1      [512]         f32
//  7 m_w2      [512,1024]    f32
//  8 m_b2      [1024]        f32
//  9 base_metric [8,128]     f32
// out [2,1024,1024] f32

// ---------------- scratch (device globals; no allocation allowed) ----------
__device__ float g_qv [2048u * 2048u];  // rows = b*1024+t, cols: [0,1024)=q (n*128+e), [1024,2048)=v
__device__ float g_sig[2048];           // [2][1024]
__device__ float g_h  [1024];           // [2][512]
__device__ float g_md [2048];           // [2][1024]  mdiag
__device__ float g_qn [2048u * 1024u];  // normalized q
__device__ float g_heb[2048u * 1024u];  // hebbian context
__device__ float g_g  [2048u * 1024u];  // q*(context+heb)

// ---------------- tiled SGEMM core: 128x128 tile, BK=16, 256 thr, 8x8 micro --
template<bool RELU>
__device__ __forceinline__ void gemm_tile_core(
    const float* __restrict__ A, int lda,    // tile base: (row0 of tile, k=0)
    const float* __restrict__ Bm, int ldb,   // tile base: (k=0, col0 of tile)
    float* __restrict__ C, int ldc, int Kdim)
{
    __shared__ float As[16][128];
    __shared__ float Bs[16][128];

    const int tid = threadIdx.x;
    const int tx = tid & 15;
    const int ty = tid >> 4;

    float acc[8][8];
#pragma unroll
    for (int i = 0; i < 8; i++)
#pragma unroll
        for (int j = 0; j < 8; j++) acc[i][j] = 0.f;

    const int arow = tid >> 2;          // 0..63  (and +64)
    const int ak   = (tid & 3) << 2;    // 0,4,8,12
    const int brow = tid >> 5;          // 0..7   (and +8)
    const int bcol = (tid & 31) << 2;   // 0..124

    for (int k0 = 0; k0 < Kdim; k0 += 16) {
        float4 a0 = *(const float4*)(A + (size_t)arow        * lda + k0 + ak);
        float4 a1 = *(const float4*)(A + (size_t)(arow + 64) * lda + k0 + ak);
        float4 b0 = *(const float4*)(Bm + (size_t)(k0 + brow)     * ldb + bcol);
        float4 b1 = *(const float4*)(Bm + (size_t)(k0 + brow + 8) * ldb + bcol);

        As[ak + 0][arow] = a0.x;  As[ak + 1][arow] = a0.y;
        As[ak + 2][arow] = a0.z;  As[ak + 3][arow] = a0.w;
        As[ak + 0][arow + 64] = a1.x;  As[ak + 1][arow + 64] = a1.y;
        As[ak + 2][arow + 64] = a1.z;  As[ak + 3][arow + 64] = a1.w;
        *(float4*)&Bs[brow][bcol]     = b0;
        *(float4*)&Bs[brow + 8][bcol] = b1;
        __syncthreads();

#pragma unroll
        for (int kk = 0; kk < 16; kk++) {
            float a[8], b[8];
            *(float4*)&a[0] = *(const float4*)&As[kk][ty * 8];
            *(float4*)&a[4] = *(const float4*)&As[kk][ty * 8 + 4];
            *(float4*)&b[0] = *(const float4*)&Bs[kk][tx * 8];
            *(float4*)&b[4] = *(const float4*)&Bs[kk][tx * 8 + 4];
#pragma unroll
            for (int i = 0; i < 8; i++)
#pragma unroll
                for (int j = 0; j < 8; j++)
                    acc[i][j] = fmaf(a[i], b[j], acc[i][j]);
        }
        __syncthreads();
    }

#pragma unroll
    for (int i = 0; i < 8; i++) {
        float* cp = C + (size_t)(ty * 8 + i) * ldc + tx * 8;
        float4 v0, v1;
        if (RELU) {
            v0.x = fmaxf(acc[i][0], 0.f); v0.y = fmaxf(acc[i][1], 0.f);
            v0.z = fmaxf(acc[i][2], 0.f); v0.w = fmaxf(acc[i][3], 0.f);
            v1.x = fmaxf(acc[i][4], 0.f); v1.y = fmaxf(acc[i][5], 0.f);
            v1.z = fmaxf(acc[i][6], 0.f); v1.w = fmaxf(acc[i][7], 0.f);
        } else {
            v0.x = acc[i][0]; v0.y = acc[i][1]; v0.z = acc[i][2]; v0.w = acc[i][3];
            v1.x = acc[i][4]; v1.y = acc[i][5]; v1.z = acc[i][6]; v1.w = acc[i][7];
        }
        *(float4*)(cp)     = v0;
        *(float4*)(cp + 4) = v1;
    }
}

// q|v = relu(x @ [enc_q|enc_v]) ; each 128-wide col-tile is exactly one head slab
__global__ void gemm_enc_kernel(const float* __restrict__ x,
                                const float* __restrict__ enc_q,
                                const float* __restrict__ enc_v)
{
    const int ct = blockIdx.x;   // 0..15 (col tile: head, q then v)
    const int rt = blockIdx.y;   // 0..15 (row tile of 2048)
    const float* A  = x + (size_t)rt * 128 * 1024;
    const float* Bp = (ct < 8) ? (enc_q + (size_t)ct * 1024 * 128)
                               : (enc_v + (size_t)(ct - 8) * 1024 * 128);
    float* C = g_qv + (size_t)rt * 128 * 2048 + ct * 128;
    gemm_tile_core<true>(A, 1024, Bp, 128, C, 2048, 1024);
}

// heb_ctx = qn @ hebbian  (block-diagonal: 8 independent 2048x128x128 GEMMs)
__global__ void gemm_heb_kernel(const float* __restrict__ heb)
{
    const int n  = blockIdx.x;   // 0..7
    const int rt = blockIdx.y;   // 0..15
    const float* A  = g_qn + (size_t)rt * 128 * 1024 + n * 128;
    const float* Bp = heb + (size_t)n * 128 * 128;
    float* C = g_heb + (size_t)rt * 128 * 1024 + n * 128;
    gemm_tile_core<false>(A, 1024, Bp, 128, C, 1024, 128);
}

// out = g @ decoder
__global__ void gemm_dec_kernel(const float* __restrict__ dec, float* __restrict__ out)
{
    const int ct = blockIdx.x;   // 0..7
    const int rt = blockIdx.y;   // 0..15
    const float* A = g_g + (size_t)rt * 128 * 1024;
    const float* Bp = dec + ct * 128;
    float* C = out + (size_t)rt * 128 * 1024 + ct * 128;
    gemm_tile_core<false>(A, 1024, Bp, 1024, C, 1024, 1024);
}

// ---------------- sig = mean_t q + 0.5*mean_{t%8==0} q ----------------------
__global__ void zero_sig_kernel() {
    g_sig[blockIdx.x * 1024 + threadIdx.x] = 0.f;
}

__global__ void sig_reduce_kernel() {
    const int b  = blockIdx.x;          // 0..1
    const int cc = blockIdx.y;          // 0..7 (128 cols)
    const int tc = blockIdx.z;          // 0..15 (64 t)
    const int c  = cc * 128 + threadIdx.x;
    float acc = 0.f;
#pragma unroll 8
    for (int tt = 0; tt < 64; tt++) {
        const int t = tc * 64 + tt;
        const float w = (1.0f / 1024.0f) + (((t & 7) == 0) ? (0.5f / 128.0f) : 0.f);
        acc += g_qv[(size_t)(b * 1024 + t) * 2048 + c] * w;
    }
    atomicAdd(&g_sig[b * 1024 + c], acc);
}

// ---------------- modulation MLP -------------------------------------------
__global__ void mlp1_kernel(const float* __restrict__ W1, const float* __restrict__ b1)
{
    __shared__ float ssig[2048];
    const int tid = threadIdx.x;  // 128
    for (int i = tid; i < 2048; i += 128) ssig[i] = g_sig[i];
    __syncthreads();
    const int b = tid >> 6;
    const int j = blockIdx.x * 64 + (tid & 63);
    float acc = b1[j];
    const float* sp = ssig + b * 1024;
#pragma unroll 8
    for (int d = 0; d < 1024; d++) acc = fmaf(sp[d], W1[(size_t)d * 512 + j], acc);
    // exact GELU
    g_h[b * 512 + j] = 0.5f * acc * (1.f + erff(acc * 0.70710678118654752f));
}

__global__ void mlp2_kernel(const float* __restrict__ W2, const float* __restrict__ b2,
                            const float* __restrict__ base_metric)
{
    __shared__ float sh[1024];
    const int tid = threadIdx.x;  // 256
    for (int i = tid; i < 1024; i += 256) sh[i] = g_h[i];
    __syncthreads();
    const int b = tid >> 7;
    const int j = blockIdx.x * 128 + (tid & 127);
    float acc = b2[j];
    const float* hp = sh + b * 512;
#pragma unroll 8
    for (int i = 0; i < 512; i++) acc = fmaf(hp[i], W2[(size_t)i * 1024 + j], acc);
    const float xv = base_metric[j] + 0.1f * acc;
    const float sp = fmaxf(xv, 0.f) + log1pf(expf(-fabsf(xv)));   // stable softplus
    g_md[b * 1024 + j] = sp + 1e-6f;
}

// ---------------- qn = q / max(||q||, 1e-12) --------------------------------
__global__ void qn_kernel()
{
    const int g    = blockIdx.x * 8 + (threadIdx.x >> 5);  // warp id: r*8+n
    const int lane = threadIdx.x & 31;
    const int r = g >> 3;
    const int n = g & 7;
    const float4 q = *(const float4*)(g_qv + (size_t)r * 2048 + n * 128 + lane * 4);
    float ss = q.x * q.x + q.y * q.y + q.z * q.z + q.w * q.w;
#pragma unroll
    for (int o = 16; o > 0; o >>= 1) ss += __shfl_xor_sync(0xffffffffu, ss, o);
    const float inv = 1.f / fmaxf(sqrtf(ss), 1e-12f);
    float4 o4 = make_float4(q.x * inv, q.y * inv, q.z * inv, q.w * inv);
    *(float4*)(g_qn + (size_t)r * 1024 + n * 128 + lane * 4) = o4;
}

// ---------------- sliding-window geometric interaction ----------------------
// warp per (b,n,t); lanes split headdim as float4 (e = lane*4..lane*4+3)
__global__ void window_kernel()
{
    const int wg   = blockIdx.x * 8 + (threadIdx.x >> 5);
    const int lane = threadIdx.x & 31;
    const int b = wg >> 13;
    const int n = (wg >> 10) & 7;
    const int t = wg & 1023;

    const float* qbase = g_qv + (size_t)b * 1024 * 2048 + n * 128;
    const float* vbase = qbase + 1024;

    const float4 md = *(const float4*)(g_md + b * 1024 + n * 128 + lane * 4);
    const float4 qc = *(const float4*)(qbase + (size_t)t * 2048 + lane * 4);

    float wk = 0.f, sumw = 0.f;
#pragma unroll 1
    for (int k = 0; k < 32; k++) {
        const int row = t - 31 + k;            // warp-uniform
        float4 w = make_float4(0.f, 0.f, 0.f, 0.f);
        if (row >= 0) w = *(const float4*)(qbase + (size_t)row * 2048 + lane * 4);
        const float dx = qc.x - w.x, dy = qc.y - w.y;
        const float dz = qc.z - w.z, dw = qc.w - w.w;
        float s = md.x * dx * dx + md.y * dy * dy + md.z * dz * dz + md.w * dw * dw;
#pragma unroll
        for (int o = 16; o > 0; o >>= 1) s += __shfl_xor_sync(0xffffffffu, s, o);
        const float e = expf(-sqrtf(s + 1e-8f));
        sumw += e;
        if (lane == k) wk = e;
    }
    const float inv = 1.f / (sumw + 1e-8f);

    float4 ctx = make_float4(0.f, 0.f, 0.f, 0.f);
#pragma unroll 1
    for (int k = 0; k < 32; k++) {
        const int row = t - 31 + k;            // warp-uniform => no divergent shfl
        const float wb = __shfl_sync(0xffffffffu, wk, k) * inv;
        if (row >= 0) {
            const float4 v = *(const float4*)(vbase + (size_t)row * 2048 + lane * 4);
            ctx.x = fmaf(wb, v.x, ctx.x); ctx.y = fmaf(wb, v.y, ctx.y);
            ctx.z = fmaf(wb, v.z, ctx.z); ctx.w = fmaf(wb, v.w, ctx.w);
        }
    }

    const size_t oidx = (size_t)(b * 1024 + t) * 1024 + n * 128 + lane * 4;
    const float4 hb = *(const float4*)(g_heb + oidx);
    float4 o4;
    o4.x = qc.x * (ctx.x + hb.x);
    o4.y = qc.y * (ctx.y + hb.y);
    o4.z = qc.z * (ctx.z + hb.z);
    o4.w = qc.w * (ctx.w + hb.w);
    *(float4*)(g_g + oidx) = o4;
}

// ---------------- launch -----------------------------------------------------
extern "C" void kernel_launch(void* const* d_in, const int* in_sizes, int n_in,
                              void* d_out, int out_size)
{
    const float* x           = (const float*)d_in[0];
    const float* enc_q       = (const float*)d_in[1];
    const float* enc_v       = (const float*)d_in[2];
    const float* decoder     = (const float*)d_in[3];
    const float* hebbian     = (const float*)d_in[4];
    const float* m_w1        = (const float*)d_in[5];
    const float* m_b1        = (const float*)d_in[6];
    const float* m_w2        = (const float*)d_in[7];
    const float* m_b2        = (const float*)d_in[8];
    const float* base_metric = (const float*)d_in[9];
    float* out = (float*)d_out;

    gemm_enc_kernel<<<dim3(16, 16), 256>>>(x, enc_q, enc_v);
    zero_sig_kernel<<<2, 1024>>>();
    sig_reduce_kernel<<<dim3(2, 8, 16), 128>>>();
    mlp1_kernel<<<8, 128>>>(m_w1, m_b1);
    mlp2_kernel<<<8, 256>>>(m_w2, m_b2, base_metric);
    qn_kernel<<<2048, 256>>>();
    gemm_heb_kernel<<<dim3(8, 16), 256>>>(hebbian);
    window_kernel<<<2048, 256>>>();
    gemm_dec_kernel<<<dim3(8, 16), 256>>>(decoder, out);
}

// round 5
// speedup vs baseline: 1.0996x; 1.0996x over previous
#include <cuda_runtime.h>
#include <math.h>

// Problem shapes (fixed): B=2, T=1024, D=1024, N=8, HD=128, K=32

// ---------------- scratch (device globals; no allocation allowed) ----------
__device__ float g_qv [2048u * 2048u];  // rows = b*1024+t, cols: [0,1024)=q (n*128+e), [1024,2048)=v
__device__ float g_sig[2048];           // [2][1024]
__device__ float g_hpre[1024];          // [2][512]  pre-activation
__device__ float g_h  [1024];           // [2][512]
__device__ float g_mdpre[2048];         // [2][1024] pre-softplus accumulator
__device__ float g_md [2048];           // [2][1024] mdiag
__device__ float g_qn [2048u * 1024u];  // normalized q
__device__ float g_heb[2048u * 1024u];  // hebbian context
__device__ float g_g  [2048u * 1024u];  // q*(context+heb)

// ---------------- tiled SGEMM core: 128x128 tile, BK=16, 256 thr, 8x8 micro --
template<bool RELU>
__device__ __forceinline__ void gemm_tile_core(
    const float* __restrict__ A, int lda,
    const float* __restrict__ Bm, int ldb,
    float* __restrict__ C, int ldc, int Kdim)
{
    __shared__ float As[16][128];
    __shared__ float Bs[16][128];

    const int tid = threadIdx.x;
    const int tx = tid & 15;
    const int ty = tid >> 4;

    float acc[8][8];
#pragma unroll
    for (int i = 0; i < 8; i++)
#pragma unroll
        for (int j = 0; j < 8; j++) acc[i][j] = 0.f;

    const int arow = tid >> 2;
    const int ak   = (tid & 3) << 2;
    const int brow = tid >> 5;
    const int bcol = (tid & 31) << 2;

    for (int k0 = 0; k0 < Kdim; k0 += 16) {
        float4 a0 = *(const float4*)(A + (size_t)arow        * lda + k0 + ak);
        float4 a1 = *(const float4*)(A + (size_t)(arow + 64) * lda + k0 + ak);
        float4 b0 = *(const float4*)(Bm + (size_t)(k0 + brow)     * ldb + bcol);
        float4 b1 = *(const float4*)(Bm + (size_t)(k0 + brow + 8) * ldb + bcol);

        As[ak + 0][arow] = a0.x;  As[ak + 1][arow] = a0.y;
        As[ak + 2][arow] = a0.z;  As[ak + 3][arow] = a0.w;
        As[ak + 0][arow + 64] = a1.x;  As[ak + 1][arow + 64] = a1.y;
        As[ak + 2][arow + 64] = a1.z;  As[ak + 3][arow + 64] = a1.w;
        *(float4*)&Bs[brow][bcol]     = b0;
        *(float4*)&Bs[brow + 8][bcol] = b1;
        __syncthreads();

#pragma unroll
        for (int kk = 0; kk < 16; kk++) {
            float a[8], b[8];
            *(float4*)&a[0] = *(const float4*)&As[kk][ty * 8];
            *(float4*)&a[4] = *(const float4*)&As[kk][ty * 8 + 4];
            *(float4*)&b[0] = *(const float4*)&Bs[kk][tx * 8];
            *(float4*)&b[4] = *(const float4*)&Bs[kk][tx * 8 + 4];
#pragma unroll
            for (int i = 0; i < 8; i++)
#pragma unroll
                for (int j = 0; j < 8; j++)
                    acc[i][j] = fmaf(a[i], b[j], acc[i][j]);
        }
        __syncthreads();
    }

#pragma unroll
    for (int i = 0; i < 8; i++) {
        float* cp = C + (size_t)(ty * 8 + i) * ldc + tx * 8;
        float4 v0, v1;
        if (RELU) {
            v0.x = fmaxf(acc[i][0], 0.f); v0.y = fmaxf(acc[i][1], 0.f);
            v0.z = fmaxf(acc[i][2], 0.f); v0.w = fmaxf(acc[i][3], 0.f);
            v1.x = fmaxf(acc[i][4], 0.f); v1.y = fmaxf(acc[i][5], 0.f);
            v1.z = fmaxf(acc[i][6], 0.f); v1.w = fmaxf(acc[i][7], 0.f);
        } else {
            v0.x = acc[i][0]; v0.y = acc[i][1]; v0.z = acc[i][2]; v0.w = acc[i][3];
            v1.x = acc[i][4]; v1.y = acc[i][5]; v1.z = acc[i][6]; v1.w = acc[i][7];
        }
        *(float4*)(cp)     = v0;
        *(float4*)(cp + 4) = v1;
    }
}

__global__ void gemm_enc_kernel(const float* __restrict__ x,
                                const float* __restrict__ enc_q,
                                const float* __restrict__ enc_v)
{
    const int ct = blockIdx.x;
    const int rt = blockIdx.y;
    const float* A  = x + (size_t)rt * 128 * 1024;
    const float* Bp = (ct < 8) ? (enc_q + (size_t)ct * 1024 * 128)
                               : (enc_v + (size_t)(ct - 8) * 1024 * 128);
    float* C = g_qv + (size_t)rt * 128 * 2048 + ct * 128;
    gemm_tile_core<true>(A, 1024, Bp, 128, C, 2048, 1024);
}

__global__ void gemm_heb_kernel(const float* __restrict__ heb)
{
    const int n  = blockIdx.x;
    const int rt = blockIdx.y;
    const float* A  = g_qn + (size_t)rt * 128 * 1024 + n * 128;
    const float* Bp = heb + (size_t)n * 128 * 128;
    float* C = g_heb + (size_t)rt * 128 * 1024 + n * 128;
    gemm_tile_core<false>(A, 1024, Bp, 128, C, 1024, 128);
}

__global__ void gemm_dec_kernel(const float* __restrict__ dec, float* __restrict__ out)
{
    const int ct = blockIdx.x;
    const int rt = blockIdx.y;
    const float* A = g_g + (size_t)rt * 128 * 1024;
    const float* Bp = dec + ct * 128;
    float* C = out + (size_t)rt * 128 * 1024 + ct * 128;
    gemm_tile_core<false>(A, 1024, Bp, 1024, C, 1024, 1024);
}

// ---------------- zero the small accumulators (one launch) ------------------
__global__ void zero_small_kernel() {
    const int i = blockIdx.x * 256 + threadIdx.x;   // grid 8 -> 2048 threads
    g_sig[i]   = 0.f;
    g_mdpre[i] = 0.f;
    if (i < 1024) g_hpre[i] = 0.f;
}

// ---------------- sig = mean_t q + 0.5*mean_{t%8==0} q ----------------------
__global__ void sig_reduce_kernel() {
    const int b  = blockIdx.x;
    const int cc = blockIdx.y;
    const int tc = blockIdx.z;
    const int c  = cc * 128 + threadIdx.x;
    float acc = 0.f;
#pragma unroll 8
    for (int tt = 0; tt < 64; tt++) {
        const int t = tc * 64 + tt;
        const float w = (1.0f / 1024.0f) + (((t & 7) == 0) ? (0.5f / 128.0f) : 0.f);
        acc += g_qv[(size_t)(b * 1024 + t) * 2048 + c] * w;
    }
    atomicAdd(&g_sig[b * 1024 + c], acc);
}

// ---------------- modulation MLP: k-split partial GEMMs ---------------------
// hpre[b][j] += sum_{d in chunk} sig[b][d] * W1[d][j]
__global__ void mlp1_partial_kernel(const float* __restrict__ W1)
{
    const int j  = blockIdx.x * 64 + threadIdx.x;   // 0..511
    const int d0 = blockIdx.y * 64;                 // 16 chunks of 64
    float acc0 = 0.f, acc1 = 0.f;
#pragma unroll 8
    for (int dd = 0; dd < 64; dd++) {
        const int d = d0 + dd;
        const float w = __ldg(W1 + (size_t)d * 512 + j);
        acc0 = fmaf(__ldg(g_sig + d),        w, acc0);
        acc1 = fmaf(__ldg(g_sig + 1024 + d), w, acc1);
    }
    atomicAdd(&g_hpre[j],       acc0);
    atomicAdd(&g_hpre[512 + j], acc1);
}

__global__ void mlp1_finish_kernel(const float* __restrict__ b1)
{
    const int i = blockIdx.x * 256 + threadIdx.x;   // grid 4 -> 1024
    const float a = g_hpre[i] + b1[i & 511];
    g_h[i] = 0.5f * a * (1.f + erff(a * 0.70710678118654752f));
}

// mdpre[b][j] += sum_{i in chunk} h[b][i] * W2[i][j]
__global__ void mlp2_partial_kernel(const float* __restrict__ W2)
{
    const int j  = blockIdx.x * 64 + threadIdx.x;   // 0..1023
    const int i0 = blockIdx.y * 64;                 // 8 chunks of 64
    float acc0 = 0.f, acc1 = 0.f;
#pragma unroll 8
    for (int ii = 0; ii < 64; ii++) {
        const int i = i0 + ii;
        const float w = __ldg(W2 + (size_t)i * 1024 + j);
        acc0 = fmaf(__ldg(g_h + i),       w, acc0);
        acc1 = fmaf(__ldg(g_h + 512 + i), w, acc1);
    }
    atomicAdd(&g_mdpre[j],        acc0);
    atomicAdd(&g_mdpre[1024 + j], acc1);
}

__global__ void mlp2_finish_kernel(const float* __restrict__ b2,
                                   const float* __restrict__ base_metric)
{
    const int i = blockIdx.x * 256 + threadIdx.x;   // grid 8 -> 2048
    const int j = i & 1023;
    const float mod = g_mdpre[i] + b2[j];
    const float xv  = base_metric[j] + 0.1f * mod;
    const float sp  = fmaxf(xv, 0.f) + log1pf(expf(-fabsf(xv)));
    g_md[i] = sp + 1e-6f;
}

// ---------------- qn = q / max(||q||, 1e-12) --------------------------------
__global__ void qn_kernel()
{
    const int g    = blockIdx.x * 8 + (threadIdx.x >> 5);
    const int lane = threadIdx.x & 31;
    const int r = g >> 3;
    const int n = g & 7;
    const float4 q = *(const float4*)(g_qv + (size_t)r * 2048 + n * 128 + lane * 4);
    float ss = q.x * q.x + q.y * q.y + q.z * q.z + q.w * q.w;
#pragma unroll
    for (int o = 16; o > 0; o >>= 1) ss += __shfl_xor_sync(0xffffffffu, ss, o);
    const float inv = 1.f / fmaxf(sqrtf(ss), 1e-12f);
    float4 o4 = make_float4(q.x * inv, q.y * inv, q.z * inv, q.w * inv);
    *(float4*)(g_qn + (size_t)r * 1024 + n * 128 + lane * 4) = o4;
}

// ---------------- sliding-window geometric interaction ----------------------
__global__ void window_kernel()
{
    const int wg   = blockIdx.x * 8 + (threadIdx.x >> 5);
    const int lane = threadIdx.x & 31;
    const int b = wg >> 13;
    const int n = (wg >> 10) & 7;
    const int t = wg & 1023;

    const float* qbase = g_qv + (size_t)b * 1024 * 2048 + n * 128;
    const float* vbase = qbase + 1024;

    const float4 md = *(const float4*)(g_md + b * 1024 + n * 128 + lane * 4);
    const float4 qc = *(const float4*)(qbase + (size_t)t * 2048 + lane * 4);

    float wk = 0.f, sumw = 0.f;
#pragma unroll 1
    for (int k = 0; k < 32; k++) {
        const int row = t - 31 + k;
        float4 w = make_float4(0.f, 0.f, 0.f, 0.f);
        if (row >= 0) w = *(const float4*)(qbase + (size_t)row * 2048 + lane * 4);
        const float dx = qc.x - w.x, dy = qc.y - w.y;
        const float dz = qc.z - w.z, dw = qc.w - w.w;
        float s = md.x * dx * dx + md.y * dy * dy + md.z * dz * dz + md.w * dw * dw;
#pragma unroll
        for (int o = 16; o > 0; o >>= 1) s += __shfl_xor_sync(0xffffffffu, s, o);
        const float e = expf(-sqrtf(s + 1e-8f));
        sumw += e;
        if (lane == k) wk = e;
    }
    const float inv = 1.f / (sumw + 1e-8f);

    float4 ctx = make_float4(0.f, 0.f, 0.f, 0.f);
#pragma unroll 1
    for (int k = 0; k < 32; k++) {
        const int row = t - 31 + k;
        const float wb = __shfl_sync(0xffffffffu, wk, k) * inv;
        if (row >= 0) {
            const float4 v = *(const float4*)(vbase + (size_t)row * 2048 + lane * 4);
            ctx.x = fmaf(wb, v.x, ctx.x); ctx.y = fmaf(wb, v.y, ctx.y);
            ctx.z = fmaf(wb, v.z, ctx.z); ctx.w = fmaf(wb, v.w, ctx.w);
        }
    }

    const size_t oidx = (size_t)(b * 1024 + t) * 1024 + n * 128 + lane * 4;
    const float4 hb = *(const float4*)(g_heb + oidx);
    float4 o4;
    o4.x = qc.x * (ctx.x + hb.x);
    o4.y = qc.y * (ctx.y + hb.y);
    o4.z = qc.z * (ctx.z + hb.z);
    o4.w = qc.w * (ctx.w + hb.w);
    *(float4*)(g_g + oidx) = o4;
}

// ---------------- launch -----------------------------------------------------
extern "C" void kernel_launch(void* const* d_in, const int* in_sizes, int n_in,
                              void* d_out, int out_size)
{
    const float* x           = (const float*)d_in[0];
    const float* enc_q       = (const float*)d_in[1];
    const float* enc_v       = (const float*)d_in[2];
    const float* decoder     = (const float*)d_in[3];
    const float* hebbian     = (const float*)d_in[4];
    const float* m_w1        = (const float*)d_in[5];
    const float* m_b1        = (const float*)d_in[6];
    const float* m_w2        = (const float*)d_in[7];
    const float* m_b2        = (const float*)d_in[8];
    const float* base_metric = (const float*)d_in[9];
    float* out = (float*)d_out;

    zero_small_kernel<<<8, 256>>>();
    gemm_enc_kernel<<<dim3(16, 16), 256>>>(x, enc_q, enc_v);
    sig_reduce_kernel<<<dim3(2, 8, 16), 128>>>();
    mlp1_partial_kernel<<<dim3(8, 16), 64>>>(m_w1);
    mlp1_finish_kernel<<<4, 256>>>(m_b1);
    mlp2_partial_kernel<<<dim3(16, 8), 64>>>(m_w2);
    mlp2_finish_kernel<<<8, 256>>>(m_b2, base_metric);
    qn_kernel<<<2048, 256>>>();
    gemm_heb_kernel<<<dim3(8, 16), 256>>>(hebbian);
    window_kernel<<<2048, 256>>>();
    gemm_dec_kernel<<<dim3(8, 16), 256>>>(decoder, out);
}

// round 7
// speedup vs baseline: 2.4617x; 2.2388x over previous
#include <cuda_runtime.h>
#include <math.h>
#include <stdint.h>

// Problem shapes (fixed): B=2, T=1024, D=1024, N=8, HD=128, K=32

// ---------------- scratch (device globals; no allocation allowed) ----------
__device__ float g_qv  [2048u * 2048u];  // rows = b*1024+t, [0,1024)=q, [1024,2048)=v
__device__ float g_xr  [2048u * 1024u];  // rna(x)
__device__ float g_encqR[8u * 1024u * 128u];  // rna(enc_q)
__device__ float g_encvR[8u * 1024u * 128u];  // rna(enc_v)
__device__ float g_decR [1024u * 1024u];      // rna(decoder)
__device__ float g_hebR [8u * 128u * 128u];   // rna(hebbian)
__device__ float g_sig[2048];
__device__ float g_hpre[1024];
__device__ float g_h  [1024];
__device__ float g_mdpre[2048];
__device__ float g_md [2048];
__device__ float g_qn [2048u * 1024u];  // normalized q (rna-rounded)
__device__ float g_heb[2048u * 1024u];
__device__ float g_g  [2048u * 1024u];  // q*(context+heb) (rna-rounded)

// ---------------- helpers ----------------------------------------------------
__device__ __forceinline__ uint32_t smem_u32(const void* p) {
    uint32_t a;
    asm("{ .reg .u64 t; cvta.to.shared.u64 t, %1; cvt.u32.u64 %0, t; }" : "=r"(a) : "l"(p));
    return a;
}
__device__ __forceinline__ float rna_tf32(float x) {
    uint32_t u; asm("cvt.rna.tf32.f32 %0, %1;" : "=r"(u) : "f"(x));
    return __uint_as_float(u);
}
__device__ __forceinline__ void cp16(uint32_t dst, const void* src) {
    asm volatile("cp.async.cg.shared.global [%0], [%1], 16;" :: "r"(dst), "l"(src) : "memory");
}
__device__ __forceinline__ void mma_tf32_16n8k8(float* c, const uint32_t* a, const uint32_t* b) {
    asm volatile(
        "mma.sync.aligned.m16n8k8.row.col.f32.tf32.tf32.f32 "
        "{%0,%1,%2,%3}, {%4,%5,%6,%7}, {%8,%9}, {%0,%1,%2,%3};"
        : "+f"(c[0]), "+f"(c[1]), "+f"(c[2]), "+f"(c[3])
        : "r"(a[0]), "r"(a[1]), "r"(a[2]), "r"(a[3]), "r"(b[0]), "r"(b[1]));
}

// ---------------- tf32 mma.sync GEMM core -----------------------------------
// 128x128 block tile, BK=32, 256 threads (8 warps: 4 in M x 2 in N),
// warp tile 32x64. A row-major [.,lda], B row-major [K][N] (ldb), both
// pre-rounded to tf32. Double-buffered cp.async smem.
#define A_STRIDE 36
#define B_STRIDE 136
#define A_SZ (128 * A_STRIDE)          // floats
#define B_SZ (32 * B_STRIDE)
#define STG_SZ (A_SZ + B_SZ)           // 8960 floats per stage
#define GEMM_SMEM_BYTES (2 * STG_SZ * 4)  // 71680 B

template<bool RELU>
__device__ void gemm_mma_core(const float* __restrict__ A, int lda,
                              const float* __restrict__ B, int ldb,
                              float* __restrict__ C, int ldc, int Kdim)
{
    extern __shared__ float smem[];
    const int tid  = threadIdx.x;
    const int lane = tid & 31;
    const int wid  = tid >> 5;
    const int wm   = wid & 3;          // 0..3 -> 32-row slab
    const int wn   = wid >> 2;         // 0..1 -> 64-col slab
    const int grp  = lane >> 2;        // 0..7
    const int tig  = lane & 3;         // 0..3

    float acc[2][8][4];
#pragma unroll
    for (int mt = 0; mt < 2; mt++)
#pragma unroll
        for (int nt = 0; nt < 8; nt++)
#pragma unroll
            for (int q = 0; q < 4; q++) acc[mt][nt][q] = 0.f;

    const int niter = Kdim >> 5;

    // stage loader: A tile 128x32, B tile 32x128
#define LOAD_STAGE(S, K0) do { \
        float* As_ = smem + (S) * STG_SZ; \
        float* Bs_ = As_ + A_SZ; \
        _Pragma("unroll") \
        for (int it = 0; it < 4; it++) { \
            const int idx = tid + (it << 8); \
            const int r_  = idx >> 3, c4_ = idx & 7; \
            cp16(smem_u32(As_ + r_ * A_STRIDE + (c4_ << 2)), \
                 A + (size_t)r_ * lda + (K0) + (c4_ << 2)); \
            const int k_ = idx >> 5, n4_ = idx & 31; \
            cp16(smem_u32(Bs_ + k_ * B_STRIDE + (n4_ << 2)), \
                 B + (size_t)((K0) + k_) * ldb + (n4_ << 2)); \
        } \
        asm volatile("cp.async.commit_group;" ::: "memory"); \
    } while (0)

    LOAD_STAGE(0, 0);

#pragma unroll 1
    for (int j = 0; j < niter; j++) {
        if (j + 1 < niter) {
            LOAD_STAGE((j + 1) & 1, (j + 1) << 5);
            asm volatile("cp.async.wait_group 1;" ::: "memory");
        } else {
            asm volatile("cp.async.wait_group 0;" ::: "memory");
        }
        __syncthreads();

        const float* As = smem + (j & 1) * STG_SZ;
        const float* Bs = As + A_SZ;

#pragma unroll
        for (int kk = 0; kk < 4; kk++) {
            const int kb = kk << 3;
            uint32_t af[2][4];
#pragma unroll
            for (int mt = 0; mt < 2; mt++) {
                const int r = wm * 32 + mt * 16 + grp;
                const float* ap = As + r * A_STRIDE + kb + tig;
                af[mt][0] = __float_as_uint(ap[0]);
                af[mt][1] = __float_as_uint(ap[8 * A_STRIDE]);
                af[mt][2] = __float_as_uint(ap[4]);
                af[mt][3] = __float_as_uint(ap[8 * A_STRIDE + 4]);
            }
            uint32_t bf[8][2];
#pragma unroll
            for (int nt = 0; nt < 8; nt++) {
                const int cc = wn * 64 + nt * 8 + grp;
                const float* bp = Bs + (kb + tig) * B_STRIDE + cc;
                bf[nt][0] = __float_as_uint(bp[0]);
                bf[nt][1] = __float_as_uint(bp[4 * B_STRIDE]);
            }
#pragma unroll
            for (int mt = 0; mt < 2; mt++)
#pragma unroll
                for (int nt = 0; nt < 8; nt++)
                    mma_tf32_16n8k8(acc[mt][nt], af[mt], bf[nt]);
        }
        __syncthreads();
    }

    // epilogue
#pragma unroll
    for (int mt = 0; mt < 2; mt++) {
        const int r0 = wm * 32 + mt * 16 + grp;
#pragma unroll
        for (int nt = 0; nt < 8; nt++) {
            const int c0 = wn * 64 + nt * 8 + tig * 2;
            float2 v0 = make_float2(acc[mt][nt][0], acc[mt][nt][1]);
            float2 v1 = make_float2(acc[mt][nt][2], acc[mt][nt][3]);
            if (RELU) {
                v0.x = fmaxf(v0.x, 0.f); v0.y = fmaxf(v0.y, 0.f);
                v1.x = fmaxf(v1.x, 0.f); v1.y = fmaxf(v1.y, 0.f);
            }
            *(float2*)(C + (size_t)r0 * ldc + c0)       = v0;
            *(float2*)(C + (size_t)(r0 + 8) * ldc + c0) = v1;
        }
    }
#undef LOAD_STAGE
}

__global__ __launch_bounds__(256) void gemm_enc_kernel()
{
    const int ct = blockIdx.x;   // 0..15: q heads then v heads
    const int mt = blockIdx.y;   // 0..15
    const float* Bp = (ct < 8) ? (g_encqR + (size_t)ct * 1024 * 128)
                               : (g_encvR + (size_t)(ct - 8) * 1024 * 128);
    gemm_mma_core<true>(g_xr + (size_t)mt * 128 * 1024, 1024, Bp, 128,
                        g_qv + (size_t)mt * 128 * 2048 + ct * 128, 2048, 1024);
}
__global__ __launch_bounds__(256) void gemm_dec_kernel(float* __restrict__ out)
{
    const int nt = blockIdx.x;   // 0..7
    const int mt = blockIdx.y;   // 0..15
    gemm_mma_core<false>(g_g + (size_t)mt * 128 * 1024, 1024,
                         g_decR + nt * 128, 1024,
                         out + (size_t)mt * 128 * 1024 + nt * 128, 1024, 1024);
}
__global__ __launch_bounds__(256) void gemm_heb_kernel()
{
    const int n  = blockIdx.x;   // 0..7 head
    const int mt = blockIdx.y;   // 0..15
    gemm_mma_core<false>(g_qn + (size_t)mt * 128 * 1024 + n * 128, 1024,
                         g_hebR + (size_t)n * 128 * 128, 128,
                         g_heb + (size_t)mt * 128 * 1024 + n * 128, 1024, 128);
}

// ---------------- pre-rounding kernels ---------------------------------------
__global__ void round_copy_kernel(const float4* __restrict__ src, float4* __restrict__ dst)
{
    const int i = blockIdx.x * 256 + threadIdx.x;
    float4 v = src[i];
    v.x = rna_tf32(v.x); v.y = rna_tf32(v.y);
    v.z = rna_tf32(v.z); v.w = rna_tf32(v.w);
    dst[i] = v;
}

// ---------------- small accumulator zero ------------------------------------
__global__ void zero_small_kernel() {
    const int i = blockIdx.x * 256 + threadIdx.x;
    g_sig[i]   = 0.f;
    g_mdpre[i] = 0.f;
    if (i < 1024) g_hpre[i] = 0.f;
}

// ---------------- sig = mean_t q + 0.5*mean_{t%8==0} q ----------------------
__global__ void sig_reduce_kernel() {
    const int b  = blockIdx.x;
    const int cc = blockIdx.y;
    const int tc = blockIdx.z;
    const int c  = cc * 128 + threadIdx.x;
    float acc = 0.f;
#pragma unroll 8
    for (int tt = 0; tt < 64; tt++) {
        const int t = tc * 64 + tt;
        const float w = (1.0f / 1024.0f) + (((t & 7) == 0) ? (0.5f / 128.0f) : 0.f);
        acc += g_qv[(size_t)(b * 1024 + t) * 2048 + c] * w;
    }
    atomicAdd(&g_sig[b * 1024 + c], acc);
}

// ---------------- modulation MLP: k-split partial GEMMs ---------------------
__global__ void mlp1_partial_kernel(const float* __restrict__ W1)
{
    const int j  = blockIdx.x * 64 + threadIdx.x;
    const int d0 = blockIdx.y * 64;
    float acc0 = 0.f, acc1 = 0.f;
#pragma unroll 8
    for (int dd = 0; dd < 64; dd++) {
        const int d = d0 + dd;
        const float w = __ldg(W1 + (size_t)d * 512 + j);
        acc0 = fmaf(__ldg(g_sig + d),        w, acc0);
        acc1 = fmaf(__ldg(g_sig + 1024 + d), w, acc1);
    }
    atomicAdd(&g_hpre[j],       acc0);
    atomicAdd(&g_hpre[512 + j], acc1);
}

__global__ void mlp1_finish_kernel(const float* __restrict__ b1)
{
    const int i = blockIdx.x * 256 + threadIdx.x;
    const float a = g_hpre[i] + b1[i & 511];
    g_h[i] = 0.5f * a * (1.f + erff(a * 0.70710678118654752f));
}

__global__ void mlp2_partial_kernel(const float* __restrict__ W2)
{
    const int j  = blockIdx.x * 64 + threadIdx.x;
    const int i0 = blockIdx.y * 64;
    float acc0 = 0.f, acc1 = 0.f;
#pragma unroll 8
    for (int ii = 0; ii < 64; ii++) {
        const int i = i0 + ii;
        const float w = __ldg(W2 + (size_t)i * 1024 + j);
        acc0 = fmaf(__ldg(g_h + i),       w, acc0);
        acc1 = fmaf(__ldg(g_h + 512 + i), w, acc1);
    }
    atomicAdd(&g_mdpre[j],        acc0);
    atomicAdd(&g_mdpre[1024 + j], acc1);
}

__global__ void mlp2_finish_kernel(const float* __restrict__ b2,
                                   const float* __restrict__ base_metric)
{
    const int i = blockIdx.x * 256 + threadIdx.x;
    const int j = i & 1023;
    const float mod = g_mdpre[i] + b2[j];
    const float xv  = base_metric[j] + 0.1f * mod;
    const float sp  = fmaxf(xv, 0.f) + log1pf(expf(-fabsf(xv)));
    g_md[i] = sp + 1e-6f;
}

// ---------------- qn = rna(q / max(||q||, 1e-12)) ---------------------------
__global__ void qn_kernel()
{
    const int g    = blockIdx.x * 8 + (threadIdx.x >> 5);
    const int lane = threadIdx.x & 31;
    const int r = g >> 3;
    const int n = g & 7;
    const float4 q = *(const float4*)(g_qv + (size_t)r * 2048 + n * 128 + lane * 4);
    float ss = q.x * q.x + q.y * q.y + q.z * q.z + q.w * q.w;
#pragma unroll
    for (int o = 16; o > 0; o >>= 1) ss += __shfl_xor_sync(0xffffffffu, ss, o);
    const float inv = 1.f / fmaxf(sqrtf(ss), 1e-12f);
    float4 o4 = make_float4(rna_tf32(q.x * inv), rna_tf32(q.y * inv),
                            rna_tf32(q.z * inv), rna_tf32(q.w * inv));
    *(float4*)(g_qn + (size_t)r * 1024 + n * 128 + lane * 4) = o4;
}

// ---------------- sliding-window geometric interaction ----------------------
__global__ void window_kernel()
{
    const int wg   = blockIdx.x * 8 + (threadIdx.x >> 5);
    const int lane = threadIdx.x & 31;
    const int b = wg >> 13;
    const int n = (wg >> 10) & 7;
    const int t = wg & 1023;

    const float* qbase = g_qv + (size_t)b * 1024 * 2048 + n * 128;
    const float* vbase = qbase + 1024;

    const float4 md = *(const float4*)(g_md + b * 1024 + n * 128 + lane * 4);
    const float4 qc = *(const float4*)(qbase + (size_t)t * 2048 + lane * 4);

    float wk = 0.f, sumw = 0.f;
#pragma unroll 1
    for (int k = 0; k < 32; k++) {
        const int row = t - 31 + k;
        float4 w = make_float4(0.f, 0.f, 0.f, 0.f);
        if (row >= 0) w = *(const float4*)(qbase + (size_t)row * 2048 + lane * 4);
        const float dx = qc.x - w.x, dy = qc.y - w.y;
        const float dz = qc.z - w.z, dw = qc.w - w.w;
        float s = md.x * dx * dx + md.y * dy * dy + md.z * dz * dz + md.w * dw * dw;
#pragma unroll
        for (int o = 16; o > 0; o >>= 1) s += __shfl_xor_sync(0xffffffffu, s, o);
        const float e = expf(-sqrtf(s + 1e-8f));
        sumw += e;
        if (lane == k) wk = e;
    }
    const float inv = 1.f / (sumw + 1e-8f);

    float4 ctx = make_float4(0.f, 0.f, 0.f, 0.f);
#pragma unroll 1
    for (int k = 0; k < 32; k++) {
        const int row = t - 31 + k;
        const float wb = __shfl_sync(0xffffffffu, wk, k) * inv;
        if (row >= 0) {
            const float4 v = *(const float4*)(vbase + (size_t)row * 2048 + lane * 4);
            ctx.x = fmaf(wb, v.x, ctx.x); ctx.y = fmaf(wb, v.y, ctx.y);
            ctx.z = fmaf(wb, v.z, ctx.z); ctx.w = fmaf(wb, v.w, ctx.w);
        }
    }

    const size_t oidx = (size_t)(b * 1024 + t) * 1024 + n * 128 + lane * 4;
    const float4 hb = *(const float4*)(g_heb + oidx);
    float4 o4;
    o4.x = rna_tf32(qc.x * (ctx.x + hb.x));
    o4.y = rna_tf32(qc.y * (ctx.y + hb.y));
    o4.z = rna_tf32(qc.z * (ctx.z + hb.z));
    o4.w = rna_tf32(qc.w * (ctx.w + hb.w));
    *(float4*)(g_g + oidx) = o4;
}

// ---------------- launch -----------------------------------------------------
extern "C" void kernel_launch(void* const* d_in, const int* in_sizes, int n_in,
                              void* d_out, int out_size)
{
    const float* x           = (const float*)d_in[0];
    const float* enc_q       = (const float*)d_in[1];
    const float* enc_v       = (const float*)d_in[2];
    const float* decoder     = (const float*)d_in[3];
    const float* hebbian     = (const float*)d_in[4];
    const float* m_w1        = (const float*)d_in[5];
    const float* m_b1        = (const float*)d_in[6];
    const float* m_w2        = (const float*)d_in[7];
    const float* m_b2        = (const float*)d_in[8];
    const float* base_metric = (const float*)d_in[9];
    float* out = (float*)d_out;

    cudaFuncSetAttribute(gemm_enc_kernel, cudaFuncAttributeMaxDynamicSharedMemorySize, GEMM_SMEM_BYTES);
    cudaFuncSetAttribute(gemm_dec_kernel, cudaFuncAttributeMaxDynamicSharedMemorySize, GEMM_SMEM_BYTES);
    cudaFuncSetAttribute(gemm_heb_kernel, cudaFuncAttributeMaxDynamicSharedMemorySize, GEMM_SMEM_BYTES);

    float *xr_p, *encq_p, *encv_p, *dec_p, *heb_p;
    cudaGetSymbolAddress((void**)&xr_p,   g_xr);
    cudaGetSymbolAddress((void**)&encq_p, g_encqR);
    cudaGetSymbolAddress((void**)&encv_p, g_encvR);
    cudaGetSymbolAddress((void**)&dec_p,  g_decR);
    cudaGetSymbolAddress((void**)&heb_p,  g_hebR);

    // pre-passes
    zero_small_kernel<<<8, 256>>>();
    round_copy_kernel<<<2048, 256>>>((const float4*)x,       (float4*)xr_p);    // 2M floats
    round_copy_kernel<<<1024, 256>>>((const float4*)enc_q,   (float4*)encq_p);  // 1M
    round_copy_kernel<<<1024, 256>>>((const float4*)enc_v,   (float4*)encv_p);  // 1M
    round_copy_kernel<<<1024, 256>>>((const float4*)decoder, (float4*)dec_p);   // 1M
    round_copy_kernel<<<128,  256>>>((const float4*)hebbian, (float4*)heb_p);   // 128K

    // main pipeline
    gemm_enc_kernel<<<dim3(16, 16), 256, GEMM_SMEM_BYTES>>>();
    sig_reduce_kernel<<<dim3(2, 8, 16), 128>>>();
    mlp1_partial_kernel<<<dim3(8, 16), 64>>>(m_w1);
    mlp1_finish_kernel<<<4, 256>>>(m_b1);
    mlp2_partial_kernel<<<dim3(16, 8), 64>>>(m_w2);
    mlp2_finish_kernel<<<8, 256>>>(m_b2, base_metric);
    qn_kernel<<<2048, 256>>>();
    gemm_heb_kernel<<<dim3(8, 16), 256, GEMM_SMEM_BYTES>>>();
    window_kernel<<<2048, 256>>>();
    gemm_dec_kernel<<<dim3(8, 16), 256, GEMM_SMEM_BYTES>>>(out);
}

// round 8
// speedup vs baseline: 2.5188x; 1.0232x over previous
#include <cuda_runtime.h>
#include <math.h>
#include <stdint.h>

// Problem shapes (fixed): B=2, T=1024, D=1024, N=8, HD=128, K=32

// ---------------- scratch (device globals; no allocation allowed) ----------
__device__ float g_qv  [2048u * 2048u];  // rows = b*1024+t, [0,1024)=q, [1024,2048)=v
__device__ float g_sig[2048];
__device__ float g_hpre[1024];
__device__ float g_h  [1024];
__device__ float g_mdpre[2048];
__device__ float g_md [2048];
__device__ float g_qn [2048u * 1024u];  // normalized q
__device__ float g_heb[2048u * 1024u];
__device__ float g_g  [2048u * 1024u];  // q*(context+heb)

// ---------------- helpers ----------------------------------------------------
__device__ __forceinline__ uint32_t smem_u32(const void* p) {
    uint32_t a;
    asm("{ .reg .u64 t; cvta.to.shared.u64 t, %1; cvt.u32.u64 %0, t; }" : "=r"(a) : "l"(p));
    return a;
}
__device__ __forceinline__ uint32_t rna_bits(float x) {
    uint32_t u; asm("cvt.rna.tf32.f32 %0, %1;" : "=r"(u) : "f"(x));
    return u;
}
__device__ __forceinline__ void cp16(uint32_t dst, const void* src) {
    asm volatile("cp.async.cg.shared.global [%0], [%1], 16;" :: "r"(dst), "l"(src) : "memory");
}
__device__ __forceinline__ void mma_tf32_16n8k8(float* c, const uint32_t* a, const uint32_t* b) {
    asm volatile(
        "mma.sync.aligned.m16n8k8.row.col.f32.tf32.tf32.f32 "
        "{%0,%1,%2,%3}, {%4,%5,%6,%7}, {%8,%9}, {%0,%1,%2,%3};"
        : "+f"(c[0]), "+f"(c[1]), "+f"(c[2]), "+f"(c[3])
        : "r"(a[0]), "r"(a[1]), "r"(a[2]), "r"(a[3]), "r"(b[0]), "r"(b[1]));
}

// ---------------- tf32 mma.sync GEMM core -----------------------------------
// 128x128 block tile, BK=32, 256 threads (8 warps: 4 in M x 2 in N),
// warp tile 32x64. A row-major [.,lda], B row-major [K][N] (ldb), raw fp32
// (RNA-rounded to tf32 at fragment load). Double-buffered cp.async smem.
// If sig != nullptr: epilogue also accumulates the time-weighted column sums
// (only valid for the RELU/enc path where rows are b-uniform per block).
#define A_STRIDE 36
#define B_STRIDE 136
#define A_SZ (128 * A_STRIDE)          // floats
#define B_SZ (32 * B_STRIDE)
#define STG_SZ (A_SZ + B_SZ)           // 8960 floats per stage
#define GEMM_SMEM_BYTES (2 * STG_SZ * 4)  // 71680 B

template<bool RELU>
__device__ void gemm_mma_core(const float* __restrict__ A, int lda,
                              const float* __restrict__ B, int ldb,
                              float* __restrict__ C, int ldc, int Kdim,
                              float* __restrict__ sig)
{
    extern __shared__ float smem[];
    const int tid  = threadIdx.x;
    const int lane = tid & 31;
    const int wid  = tid >> 5;
    const int wm   = wid & 3;          // 0..3 -> 32-row slab
    const int wn   = wid >> 2;         // 0..1 -> 64-col slab
    const int grp  = lane >> 2;        // 0..7
    const int tig  = lane & 3;         // 0..3

    float acc[2][8][4];
#pragma unroll
    for (int mt = 0; mt < 2; mt++)
#pragma unroll
        for (int nt = 0; nt < 8; nt++)
#pragma unroll
            for (int q = 0; q < 4; q++) acc[mt][nt][q] = 0.f;

    const int niter = Kdim >> 5;

#define LOAD_STAGE(S, K0) do { \
        float* As_ = smem + (S) * STG_SZ; \
        float* Bs_ = As_ + A_SZ; \
        _Pragma("unroll") \
        for (int it = 0; it < 4; it++) { \
            const int idx = tid + (it << 8); \
            const int r_  = idx >> 3, c4_ = idx & 7; \
            cp16(smem_u32(As_ + r_ * A_STRIDE + (c4_ << 2)), \
                 A + (size_t)r_ * lda + (K0) + (c4_ << 2)); \
            const int k_ = idx >> 5, n4_ = idx & 31; \
            cp16(smem_u32(Bs_ + k_ * B_STRIDE + (n4_ << 2)), \
                 B + (size_t)((K0) + k_) * ldb + (n4_ << 2)); \
        } \
        asm volatile("cp.async.commit_group;" ::: "memory"); \
    } while (0)

    LOAD_STAGE(0, 0);

#pragma unroll 1
    for (int j = 0; j < niter; j++) {
        if (j + 1 < niter) {
            LOAD_STAGE((j + 1) & 1, (j + 1) << 5);
            asm volatile("cp.async.wait_group 1;" ::: "memory");
        } else {
            asm volatile("cp.async.wait_group 0;" ::: "memory");
        }
        __syncthreads();

        const float* As = smem + (j & 1) * STG_SZ;
        const float* Bs = As + A_SZ;

#pragma unroll
        for (int kk = 0; kk < 4; kk++) {
            const int kb = kk << 3;
            uint32_t af[2][4];
#pragma unroll
            for (int mt = 0; mt < 2; mt++) {
                const int r = wm * 32 + mt * 16 + grp;
                const float* ap = As + r * A_STRIDE + kb + tig;
                af[mt][0] = rna_bits(ap[0]);
                af[mt][1] = rna_bits(ap[8 * A_STRIDE]);
                af[mt][2] = rna_bits(ap[4]);
                af[mt][3] = rna_bits(ap[8 * A_STRIDE + 4]);
            }
            uint32_t bf[8][2];
#pragma unroll
            for (int nt = 0; nt < 8; nt++) {
                const int cc = wn * 64 + nt * 8 + grp;
                const float* bp = Bs + (kb + tig) * B_STRIDE + cc;
                bf[nt][0] = rna_bits(bp[0]);
                bf[nt][1] = rna_bits(bp[4 * B_STRIDE]);
            }
#pragma unroll
            for (int mt = 0; mt < 2; mt++)
#pragma unroll
                for (int nt = 0; nt < 8; nt++)
                    mma_tf32_16n8k8(acc[mt][nt], af[mt], bf[nt]);
        }
        __syncthreads();
    }

    // epilogue (+ optional fused sig accumulation)
    float csum[8][2];
#pragma unroll
    for (int nt = 0; nt < 8; nt++) { csum[nt][0] = 0.f; csum[nt][1] = 0.f; }

#pragma unroll
    for (int mt = 0; mt < 2; mt++) {
        const int r0 = wm * 32 + mt * 16 + grp;
#pragma unroll
        for (int nt = 0; nt < 8; nt++) {
            const int c0 = wn * 64 + nt * 8 + tig * 2;
            float2 v0 = make_float2(acc[mt][nt][0], acc[mt][nt][1]);
            float2 v1 = make_float2(acc[mt][nt][2], acc[mt][nt][3]);
            if (RELU) {
                v0.x = fmaxf(v0.x, 0.f); v0.y = fmaxf(v0.y, 0.f);
                v1.x = fmaxf(v1.x, 0.f); v1.y = fmaxf(v1.y, 0.f);
            }
            if (sig) {
                csum[nt][0] += v0.x + v1.x;
                csum[nt][1] += v0.y + v1.y;
            }
            *(float2*)(C + (size_t)r0 * ldc + c0)       = v0;
            *(float2*)(C + (size_t)(r0 + 8) * ldc + c0) = v1;
        }
    }

    if (sig) {
        // thread's 4 rows are all == grp (mod 8) -> uniform time-weight
        const float w = (1.0f / 1024.0f) + ((grp == 0) ? (0.5f / 128.0f) : 0.f);
        float* sred = smem;      // safe: all threads past final k-loop sync
        if (tid < 128) sred[tid] = 0.f;
        __syncthreads();
#pragma unroll
        for (int nt = 0; nt < 8; nt++) {
            atomicAdd(&sred[wn * 64 + nt * 8 + tig * 2],     w * csum[nt][0]);
            atomicAdd(&sred[wn * 64 + nt * 8 + tig * 2 + 1], w * csum[nt][1]);
        }
        __syncthreads();
        if (tid < 128) atomicAdd(sig + tid, sred[tid]);
    }
#undef LOAD_STAGE
}

__global__ __launch_bounds__(256) void gemm_enc_kernel(
    const float* __restrict__ x, const float* __restrict__ enc_q,
    const float* __restrict__ enc_v)
{
    const int ct = blockIdx.x;   // 0..15: q heads then v heads
    const int mt = blockIdx.y;   // 0..15
    const float* Bp = (ct < 8) ? (enc_q + (size_t)ct * 1024 * 128)
                               : (enc_v + (size_t)(ct - 8) * 1024 * 128);
    float* sig = (ct < 8) ? (g_sig + (mt >> 3) * 1024 + ct * 128) : nullptr;
    gemm_mma_core<true>(x + (size_t)mt * 128 * 1024, 1024, Bp, 128,
                        g_qv + (size_t)mt * 128 * 2048 + ct * 128, 2048, 1024, sig);
}
__global__ __launch_bounds__(256) void gemm_dec_kernel(
    const float* __restrict__ dec, float* __restrict__ out)
{
    const int nt = blockIdx.x;   // 0..7
    const int mt = blockIdx.y;   // 0..15
    gemm_mma_core<false>(g_g + (size_t)mt * 128 * 1024, 1024,
                         dec + nt * 128, 1024,
                         out + (size_t)mt * 128 * 1024 + nt * 128, 1024, 1024, nullptr);
}
__global__ __launch_bounds__(256) void gemm_heb_kernel(const float* __restrict__ heb)
{
    const int n  = blockIdx.x;   // 0..7 head
    const int mt = blockIdx.y;   // 0..15
    gemm_mma_core<false>(g_qn + (size_t)mt * 128 * 1024 + n * 128, 1024,
                         heb + (size_t)n * 128 * 128, 128,
                         g_heb + (size_t)mt * 128 * 1024 + n * 128, 1024, 128, nullptr);
}

// ---------------- small accumulator zero ------------------------------------
__global__ void zero_small_kernel() {
    const int i = blockIdx.x * 256 + threadIdx.x;
    g_sig[i]   = 0.f;
    g_mdpre[i] = 0.f;
    if (i < 1024) g_hpre[i] = 0.f;
}

// ---------------- modulation MLP: k-split partial GEMMs ---------------------
__global__ void mlp1_partial_kernel(const float* __restrict__ W1)
{
    const int j  = blockIdx.x * 64 + threadIdx.x;
    const int d0 = blockIdx.y * 64;
    float acc0 = 0.f, acc1 = 0.f;
#pragma unroll 8
    for (int dd = 0; dd < 64; dd++) {
        const int d = d0 + dd;
        const float w = __ldg(W1 + (size_t)d * 512 + j);
        acc0 = fmaf(__ldg(g_sig + d),        w, acc0);
        acc1 = fmaf(__ldg(g_sig + 1024 + d), w, acc1);
    }
    atomicAdd(&g_hpre[j],       acc0);
    atomicAdd(&g_hpre[512 + j], acc1);
}

__global__ void mlp1_finish_kernel(const float* __restrict__ b1)
{
    const int i = blockIdx.x * 256 + threadIdx.x;
    const float a = g_hpre[i] + b1[i & 511];
    g_h[i] = 0.5f * a * (1.f + erff(a * 0.70710678118654752f));
}

__global__ void mlp2_partial_kernel(const float* __restrict__ W2)
{
    const int j  = blockIdx.x * 64 + threadIdx.x;
    const int i0 = blockIdx.y * 64;
    float acc0 = 0.f, acc1 = 0.f;
#pragma unroll 8
    for (int ii = 0; ii < 64; ii++) {
        const int i = i0 + ii;
        const float w = __ldg(W2 + (size_t)i * 1024 + j);
        acc0 = fmaf(__ldg(g_h + i),       w, acc0);
        acc1 = fmaf(__ldg(g_h + 512 + i), w, acc1);
    }
    atomicAdd(&g_mdpre[j],        acc0);
    atomicAdd(&g_mdpre[1024 + j], acc1);
}

__global__ void mlp2_finish_kernel(const float* __restrict__ b2,
                                   const float* __restrict__ base_metric)
{
    const int i = blockIdx.x * 256 + threadIdx.x;
    const int j = i & 1023;
    const float mod = g_mdpre[i] + b2[j];
    const float xv  = base_metric[j] + 0.1f * mod;
    const float sp  = fmaxf(xv, 0.f) + log1pf(expf(-fabsf(xv)));
    g_md[i] = sp + 1e-6f;
}

// ---------------- qn = q / max(||q||, 1e-12) --------------------------------
__global__ void qn_kernel()
{
    const int g    = blockIdx.x * 8 + (threadIdx.x >> 5);
    const int lane = threadIdx.x & 31;
    const int r = g >> 3;
    const int n = g & 7;
    const float4 q = *(const float4*)(g_qv + (size_t)r * 2048 + n * 128 + lane * 4);
    float ss = q.x * q.x + q.y * q.y + q.z * q.z + q.w * q.w;
#pragma unroll
    for (int o = 16; o > 0; o >>= 1) ss += __shfl_xor_sync(0xffffffffu, ss, o);
    const float inv = 1.f / fmaxf(sqrtf(ss), 1e-12f);
    float4 o4 = make_float4(q.x * inv, q.y * inv, q.z * inv, q.w * inv);
    *(float4*)(g_qn + (size_t)r * 1024 + n * 128 + lane * 4) = o4;
}

// ---------------- sliding-window geometric interaction ----------------------
__global__ void window_kernel()
{
    const int wg   = blockIdx.x * 8 + (threadIdx.x >> 5);
    const int lane = threadIdx.x & 31;
    const int b = wg >> 13;
    const int n = (wg >> 10) & 7;
    const int t = wg & 1023;

    const float* qbase = g_qv + (size_t)b * 1024 * 2048 + n * 128;
    const float* vbase = qbase + 1024;

    const float4 md = *(const float4*)(g_md + b * 1024 + n * 128 + lane * 4);
    const float4 qc = *(const float4*)(qbase + (size_t)t * 2048 + lane * 4);

    float wk = 0.f, sumw = 0.f;
#pragma unroll 1
    for (int k = 0; k < 32; k++) {
        const int row = t - 31 + k;
        float4 w = make_float4(0.f, 0.f, 0.f, 0.f);
        if (row >= 0) w = *(const float4*)(qbase + (size_t)row * 2048 + lane * 4);
        const float dx = qc.x - w.x, dy = qc.y - w.y;
        const float dz = qc.z - w.z, dw = qc.w - w.w;
        float s = md.x * dx * dx + md.y * dy * dy + md.z * dz * dz + md.w * dw * dw;
#pragma unroll
        for (int o = 16; o > 0; o >>= 1) s += __shfl_xor_sync(0xffffffffu, s, o);
        const float e = __expf(-sqrtf(s + 1e-8f));
        sumw += e;
        if (lane == k) wk = e;
    }
    const float inv = 1.f / (sumw + 1e-8f);

    float4 ctx = make_float4(0.f, 0.f, 0.f, 0.f);
#pragma unroll 1
    for (int k = 0; k < 32; k++) {
        const int row = t - 31 + k;
        const float wb = __shfl_sync(0xffffffffu, wk, k) * inv;
        if (row >= 0) {
            const float4 v = *(const float4*)(vbase + (size_t)row * 2048 + lane * 4);
            ctx.x = fmaf(wb, v.x, ctx.x); ctx.y = fmaf(wb, v.y, ctx.y);
            ctx.z = fmaf(wb, v.z, ctx.z); ctx.w = fmaf(wb, v.w, ctx.w);
        }
    }

    const size_t oidx = (size_t)(b * 1024 + t) * 1024 + n * 128 + lane * 4;
    const float4 hb = *(const float4*)(g_heb + oidx);
    float4 o4;
    o4.x = qc.x * (ctx.x + hb.x);
    o4.y = qc.y * (ctx.y + hb.y);
    o4.z = qc.z * (ctx.z + hb.z);
    o4.w = qc.w * (ctx.w + hb.w);
    *(float4*)(g_g + oidx) = o4;
}

// ---------------- launch -----------------------------------------------------
extern "C" void kernel_launch(void* const* d_in, const int* in_sizes, int n_in,
                              void* d_out, int out_size)
{
    const float* x           = (const float*)d_in[0];
    const float* enc_q       = (const float*)d_in[1];
    const float* enc_v       = (const float*)d_in[2];
    const float* decoder     = (const float*)d_in[3];
    const float* hebbian     = (const float*)d_in[4];
    const float* m_w1        = (const float*)d_in[5];
    const float* m_b1        = (const float*)d_in[6];
    const float* m_w2        = (const float*)d_in[7];
    const float* m_b2        = (const float*)d_in[8];
    const float* base_metric = (const float*)d_in[9];
    float* out = (float*)d_out;

    cudaFuncSetAttribute(gemm_enc_kernel, cudaFuncAttributeMaxDynamicSharedMemorySize, GEMM_SMEM_BYTES);
    cudaFuncSetAttribute(gemm_dec_kernel, cudaFuncAttributeMaxDynamicSharedMemorySize, GEMM_SMEM_BYTES);
    cudaFuncSetAttribute(gemm_heb_kernel, cudaFuncAttributeMaxDynamicSharedMemorySize, GEMM_SMEM_BYTES);

    zero_small_kernel<<<8, 256>>>();
    gemm_enc_kernel<<<dim3(16, 16), 256, GEMM_SMEM_BYTES>>>(x, enc_q, enc_v);
    mlp1_partial_kernel<<<dim3(8, 16), 64>>>(m_w1);
    mlp1_finish_kernel<<<4, 256>>>(m_b1);
    mlp2_partial_kernel<<<dim3(16, 8), 64>>>(m_w2);
    mlp2_finish_kernel<<<8, 256>>>(m_b2, base_metric);
    qn_kernel<<<2048, 256>>>();
    gemm_heb_kernel<<<dim3(8, 16), 256, GEMM_SMEM_BYTES>>>(hebbian);
    window_kernel<<<2048, 256>>>();
    gemm_dec_kernel<<<dim3(8, 16), 256, GEMM_SMEM_BYTES>>>(decoder, out);
}

// round 9
// speedup vs baseline: 2.6262x; 1.0426x over previous
#include <cuda_runtime.h>
#include <math.h>
#include <stdint.h>

// Problem shapes (fixed): B=2, T=1024, D=1024, N=8, HD=128, K=32

// ---------------- scratch (device globals; no allocation allowed) ----------
__device__ float g_qv  [2048u * 2048u];  // rows = b*1024+t, [0,1024)=q, [1024,2048)=v
__device__ float g_sigp[16u * 1024u];    // sig partials: [mt][ct*128+c] (ct<8)
__device__ float g_h1p [16u * 1024u];    // mlp1 partials: [dchunk][b*512+j]
__device__ float g_h   [1024];           // [2][512]
__device__ float g_h2p [8u * 2048u];     // mlp2 partials: [ichunk][b*1024+j]
__device__ float g_md  [2048];           // [2][1024]
__device__ float g_heb [2048u * 1024u];  // hebbian context (un-normalized q basis)
__device__ float g_g   [2048u * 1024u];  // q*(context+heb)
__device__ unsigned g_c1 = 0, g_c2 = 0;  // last-block counters (self-resetting)

// ---------------- helpers ----------------------------------------------------
__device__ __forceinline__ uint32_t smem_u32(const void* p) {
    uint32_t a;
    asm("{ .reg .u64 t; cvta.to.shared.u64 t, %1; cvt.u32.u64 %0, t; }" : "=r"(a) : "l"(p));
    return a;
}
__device__ __forceinline__ uint32_t rna_bits(float x) {
    uint32_t u; asm("cvt.rna.tf32.f32 %0, %1;" : "=r"(u) : "f"(x));
    return u;
}
__device__ __forceinline__ void cp16(uint32_t dst, const void* src) {
    asm volatile("cp.async.cg.shared.global [%0], [%1], 16;" :: "r"(dst), "l"(src) : "memory");
}
__device__ __forceinline__ void mma_tf32_16n8k8(float* c, const uint32_t* a, const uint32_t* b) {
    asm volatile(
        "mma.sync.aligned.m16n8k8.row.col.f32.tf32.tf32.f32 "
        "{%0,%1,%2,%3}, {%4,%5,%6,%7}, {%8,%9}, {%0,%1,%2,%3};"
        : "+f"(c[0]), "+f"(c[1]), "+f"(c[2]), "+f"(c[3])
        : "r"(a[0]), "r"(a[1]), "r"(a[2]), "r"(a[3]), "r"(b[0]), "r"(b[1]));
}

// ---------------- tf32 mma.sync GEMM core -----------------------------------
// 128x128 block tile, BK=32, 256 threads (8 warps: 4 in M x 2 in N),
// warp tile 32x64. A row-major [.,lda], B row-major [K][N] (ldb), raw fp32
// (RNA-rounded to tf32 at fragment load). Double-buffered cp.async smem.
// sigp != nullptr (enc/q path only): writes the time-weighted column sums of
// this 128-row tile to sigp[0..127] (non-atomic; one block owns the slot).
#define A_STRIDE 36
#define B_STRIDE 136
#define A_SZ (128 * A_STRIDE)          // floats
#define B_SZ (32 * B_STRIDE)
#define STG_SZ (A_SZ + B_SZ)           // 8960 floats per stage
#define GEMM_SMEM_BYTES (2 * STG_SZ * 4)  // 71680 B

template<bool RELU>
__device__ void gemm_mma_core(const float* __restrict__ A, int lda,
                              const float* __restrict__ B, int ldb,
                              float* __restrict__ C, int ldc, int Kdim,
                              float* __restrict__ sigp)
{
    extern __shared__ float smem[];
    const int tid  = threadIdx.x;
    const int lane = tid & 31;
    const int wid  = tid >> 5;
    const int wm   = wid & 3;          // 0..3 -> 32-row slab
    const int wn   = wid >> 2;         // 0..1 -> 64-col slab
    const int grp  = lane >> 2;        // 0..7
    const int tig  = lane & 3;         // 0..3

    float acc[2][8][4];
#pragma unroll
    for (int mt = 0; mt < 2; mt++)
#pragma unroll
        for (int nt = 0; nt < 8; nt++)
#pragma unroll
            for (int q = 0; q < 4; q++) acc[mt][nt][q] = 0.f;

    const int niter = Kdim >> 5;

#define LOAD_STAGE(S, K0) do { \
        float* As_ = smem + (S) * STG_SZ; \
        float* Bs_ = As_ + A_SZ; \
        _Pragma("unroll") \
        for (int it = 0; it < 4; it++) { \
            const int idx = tid + (it << 8); \
            const int r_  = idx >> 3, c4_ = idx & 7; \
            cp16(smem_u32(As_ + r_ * A_STRIDE + (c4_ << 2)), \
                 A + (size_t)r_ * lda + (K0) + (c4_ << 2)); \
            const int k_ = idx >> 5, n4_ = idx & 31; \
            cp16(smem_u32(Bs_ + k_ * B_STRIDE + (n4_ << 2)), \
                 B + (size_t)((K0) + k_) * ldb + (n4_ << 2)); \
        } \
        asm volatile("cp.async.commit_group;" ::: "memory"); \
    } while (0)

    LOAD_STAGE(0, 0);

#pragma unroll 1
    for (int j = 0; j < niter; j++) {
        if (j + 1 < niter) {
            LOAD_STAGE((j + 1) & 1, (j + 1) << 5);
            asm volatile("cp.async.wait_group 1;" ::: "memory");
        } else {
            asm volatile("cp.async.wait_group 0;" ::: "memory");
        }
        __syncthreads();

        const float* As = smem + (j & 1) * STG_SZ;
        const float* Bs = As + A_SZ;

#pragma unroll
        for (int kk = 0; kk < 4; kk++) {
            const int kb = kk << 3;
            uint32_t af[2][4];
#pragma unroll
            for (int mt = 0; mt < 2; mt++) {
                const int r = wm * 32 + mt * 16 + grp;
                const float* ap = As + r * A_STRIDE + kb + tig;
                af[mt][0] = rna_bits(ap[0]);
                af[mt][1] = rna_bits(ap[8 * A_STRIDE]);
                af[mt][2] = rna_bits(ap[4]);
                af[mt][3] = rna_bits(ap[8 * A_STRIDE + 4]);
            }
            uint32_t bf[8][2];
#pragma unroll
            for (int nt = 0; nt < 8; nt++) {
                const int cc = wn * 64 + nt * 8 + grp;
                const float* bp = Bs + (kb + tig) * B_STRIDE + cc;
                bf[nt][0] = rna_bits(bp[0]);
                bf[nt][1] = rna_bits(bp[4 * B_STRIDE]);
            }
#pragma unroll
            for (int mt = 0; mt < 2; mt++)
#pragma unroll
                for (int nt = 0; nt < 8; nt++)
                    mma_tf32_16n8k8(acc[mt][nt], af[mt], bf[nt]);
        }
        __syncthreads();
    }

    // epilogue (+ optional fused sig accumulation)
    float csum[8][2];
#pragma unroll
    for (int nt = 0; nt < 8; nt++) { csum[nt][0] = 0.f; csum[nt][1] = 0.f; }

#pragma unroll
    for (int mt = 0; mt < 2; mt++) {
        const int r0 = wm * 32 + mt * 16 + grp;
#pragma unroll
        for (int nt = 0; nt < 8; nt++) {
            const int c0 = wn * 64 + nt * 8 + tig * 2;
            float2 v0 = make_float2(acc[mt][nt][0], acc[mt][nt][1]);
            float2 v1 = make_float2(acc[mt][nt][2], acc[mt][nt][3]);
            if (RELU) {
                v0.x = fmaxf(v0.x, 0.f); v0.y = fmaxf(v0.y, 0.f);
                v1.x = fmaxf(v1.x, 0.f); v1.y = fmaxf(v1.y, 0.f);
            }
            if (sigp) {
                csum[nt][0] += v0.x + v1.x;
                csum[nt][1] += v0.y + v1.y;
            }
            *(float2*)(C + (size_t)r0 * ldc + c0)       = v0;
            *(float2*)(C + (size_t)(r0 + 8) * ldc + c0) = v1;
        }
    }

    if (sigp) {
        // thread's 4 rows are all == grp (mod 8) -> uniform time-weight
        const float w = (1.0f / 1024.0f) + ((grp == 0) ? (0.5f / 128.0f) : 0.f);
        float* sred = smem;      // safe: all threads past final k-loop sync
        if (tid < 128) sred[tid] = 0.f;
        __syncthreads();
#pragma unroll
        for (int nt = 0; nt < 8; nt++) {
            atomicAdd(&sred[wn * 64 + nt * 8 + tig * 2],     w * csum[nt][0]);
            atomicAdd(&sred[wn * 64 + nt * 8 + tig * 2 + 1], w * csum[nt][1]);
        }
        __syncthreads();
        if (tid < 128) sigp[tid] = sred[tid];   // non-atomic: block owns slot
    }
#undef LOAD_STAGE
}

__global__ __launch_bounds__(256) void gemm_enc_kernel(
    const float* __restrict__ x, const float* __restrict__ enc_q,
    const float* __restrict__ enc_v)
{
    const int ct = blockIdx.x;   // 0..15: q heads then v heads
    const int mt = blockIdx.y;   // 0..15
    const float* Bp = (ct < 8) ? (enc_q + (size_t)ct * 1024 * 128)
                               : (enc_v + (size_t)(ct - 8) * 1024 * 128);
    float* sigp = (ct < 8) ? (g_sigp + mt * 1024 + ct * 128) : nullptr;
    gemm_mma_core<true>(x + (size_t)mt * 128 * 1024, 1024, Bp, 128,
                        g_qv + (size_t)mt * 128 * 2048 + ct * 128, 2048, 1024, sigp);
}
__global__ __launch_bounds__(256) void gemm_dec_kernel(
    const float* __restrict__ dec, float* __restrict__ out)
{
    const int nt = blockIdx.x;   // 0..7
    const int mt = blockIdx.y;   // 0..15
    gemm_mma_core<false>(g_g + (size_t)mt * 128 * 1024, 1024,
                         dec + nt * 128, 1024,
                         out + (size_t)mt * 128 * 1024 + nt * 128, 1024, 1024, nullptr);
}
// heb GEMM on RAW q (normalization deferred to window kernel: row-scaling
// commutes with the GEMM).
__global__ __launch_bounds__(256) void gemm_heb_kernel(const float* __restrict__ heb)
{
    const int n  = blockIdx.x;   // 0..7 head
    const int mt = blockIdx.y;   // 0..15
    gemm_mma_core<false>(g_qv + (size_t)mt * 128 * 2048 + n * 128, 2048,
                         heb + (size_t)n * 128 * 128, 128,
                         g_heb + (size_t)mt * 128 * 1024 + n * 128, 1024, 128, nullptr);
}

// ---------------- MLP layer 1: partial GEMM + last-block finish -------------
// grid 32: bid = jb (0..1) | dc<<1 (0..15).  256 threads: one j each, both b.
__global__ void mlp1_kernel(const float* __restrict__ W1, const float* __restrict__ b1)
{
    __shared__ float ssig[2][64];
    __shared__ bool is_last;
    const int tid = threadIdx.x;
    const int jb  = blockIdx.x & 1;
    const int dc  = blockIdx.x >> 1;

    // gather sig chunk: sum 8 tile-partials per (b, d)
    if (tid < 128) {
        const int b = tid >> 6, dl = tid & 63;
        float s = 0.f;
#pragma unroll
        for (int m = 0; m < 8; m++)
            s += g_sigp[(b * 8 + m) * 1024 + dc * 64 + dl];
        ssig[b][dl] = s;
    }
    __syncthreads();

    const int j = jb * 256 + tid;
    float acc0 = 0.f, acc1 = 0.f;
#pragma unroll 8
    for (int dd = 0; dd < 64; dd++) {
        const float w = __ldg(W1 + (size_t)(dc * 64 + dd) * 512 + j);
        acc0 = fmaf(ssig[0][dd], w, acc0);
        acc1 = fmaf(ssig[1][dd], w, acc1);
    }
    g_h1p[dc * 1024 + j]       = acc0;
    g_h1p[dc * 1024 + 512 + j] = acc1;

    __threadfence();
    if (tid == 0) is_last = (atomicAdd(&g_c1, 1u) == 31u);
    __syncthreads();
    if (is_last) {
#pragma unroll
        for (int q = 0; q < 4; q++) {
            const int i = q * 256 + tid;       // 0..1023 = b*512+j
            float a = b1[i & 511];
#pragma unroll
            for (int c = 0; c < 16; c++) a += g_h1p[c * 1024 + i];
            g_h[i] = 0.5f * a * (1.f + erff(a * 0.70710678118654752f));
        }
        __threadfence();
        if (tid == 0) g_c1 = 0u;
    }
}

// ---------------- MLP layer 2: partial GEMM + last-block finish -------------
// grid 32: bid = jb (0..3) | ic<<2 (0..7).  256 threads.
__global__ void mlp2_kernel(const float* __restrict__ W2, const float* __restrict__ b2,
                            const float* __restrict__ base_metric)
{
    __shared__ float sh[2][64];
    __shared__ bool is_last;
    const int tid = threadIdx.x;
    const int jb  = blockIdx.x & 3;
    const int ic  = blockIdx.x >> 2;

    if (tid < 128) {
        const int b = tid >> 6, il = tid & 63;
        sh[b][il] = g_h[b * 512 + ic * 64 + il];
    }
    __syncthreads();

    const int j = jb * 256 + tid;
    float acc0 = 0.f, acc1 = 0.f;
#pragma unroll 8
    for (int ii = 0; ii < 64; ii++) {
        const float w = __ldg(W2 + (size_t)(ic * 64 + ii) * 1024 + j);
        acc0 = fmaf(sh[0][ii], w, acc0);
        acc1 = fmaf(sh[1][ii], w, acc1);
    }
    g_h2p[ic * 2048 + j]        = acc0;
    g_h2p[ic * 2048 + 1024 + j] = acc1;

    __threadfence();
    if (tid == 0) is_last = (atomicAdd(&g_c2, 1u) == 31u);
    __syncthreads();
    if (is_last) {
#pragma unroll
        for (int q = 0; q < 8; q++) {
            const int i = q * 256 + tid;       // 0..2047 = b*1024+j
            const int jj = i & 1023;
            float mod = b2[jj];
#pragma unroll
            for (int c = 0; c < 8; c++) mod += g_h2p[c * 2048 + i];
            const float xv = base_metric[jj] + 0.1f * mod;
            const float sp = fmaxf(xv, 0.f) + log1pf(expf(-fabsf(xv)));
            g_md[i] = sp + 1e-6f;
        }
        __threadfence();
        if (tid == 0) g_c2 = 0u;
    }
}

// ---------------- sliding-window geometric interaction ----------------------
// warp per (b,n,t). Phase 1: per-lane distance partials -> smem transpose ->
// lane k owns dist_k/e_k. Also normalizes the hebbian term (q-norm computed
// here instead of a separate qn kernel).
__global__ __launch_bounds__(256) void window_kernel()
{
    __shared__ float buf[8][32][33];
    const int widx = threadIdx.x >> 5;
    const int lane = threadIdx.x & 31;
    const int wg   = blockIdx.x * 8 + widx;
    const int b = wg >> 13;
    const int n = (wg >> 10) & 7;
    const int t = wg & 1023;

    const float* qbase = g_qv + (size_t)b * 1024 * 2048 + n * 128;
    const float* vbase = qbase + 1024;

    const float4 md = *(const float4*)(g_md + b * 1024 + n * 128 + lane * 4);
    const float4 qc = *(const float4*)(qbase + (size_t)t * 2048 + lane * 4);

    float (*mybuf)[33] = buf[widx];

    // phase 1: per-lane partial distances for all 32 window slots
#pragma unroll 1
    for (int k = 0; k < 32; k++) {
        const int row = t - 31 + k;
        float4 w = make_float4(0.f, 0.f, 0.f, 0.f);
        if (row >= 0) w = *(const float4*)(qbase + (size_t)row * 2048 + lane * 4);
        const float dx = qc.x - w.x, dy = qc.y - w.y;
        const float dz = qc.z - w.z, dw = qc.w - w.w;
        mybuf[k][lane] = md.x * dx * dx + md.y * dy * dy + md.z * dz * dz + md.w * dw * dw;
    }
    __syncwarp();

    // transpose-reduce: lane L sums window slot k=L (conflict-free, stride 33)
    float d0 = 0.f, d1 = 0.f, d2 = 0.f, d3 = 0.f;
#pragma unroll
    for (int i = 0; i < 32; i += 4) {
        d0 += mybuf[lane][i];     d1 += mybuf[lane][i + 1];
        d2 += mybuf[lane][i + 2]; d3 += mybuf[lane][i + 3];
    }
    const float e = __expf(-sqrtf((d0 + d1) + (d2 + d3) + 1e-8f));

    float sumw = e;
    float nq = qc.x * qc.x + qc.y * qc.y + qc.z * qc.z + qc.w * qc.w;
#pragma unroll
    for (int o = 16; o > 0; o >>= 1) {
        sumw += __shfl_xor_sync(0xffffffffu, sumw, o);
        nq   += __shfl_xor_sync(0xffffffffu, nq, o);
    }
    const float inv  = 1.f / (sumw + 1e-8f);
    const float invn = 1.f / fmaxf(sqrtf(nq), 1e-12f);

    // phase 2: weighted value aggregation
    float4 ctx = make_float4(0.f, 0.f, 0.f, 0.f);
#pragma unroll 1
    for (int k = 0; k < 32; k++) {
        const int row = t - 31 + k;
        const float wb = __shfl_sync(0xffffffffu, e, k) * inv;
        if (row >= 0) {
            const float4 v = *(const float4*)(vbase + (size_t)row * 2048 + lane * 4);
            ctx.x = fmaf(wb, v.x, ctx.x); ctx.y = fmaf(wb, v.y, ctx.y);
            ctx.z = fmaf(wb, v.z, ctx.z); ctx.w = fmaf(wb, v.w, ctx.w);
        }
    }

    const size_t oidx = (size_t)(b * 1024 + t) * 1024 + n * 128 + lane * 4;
    const float4 hb = *(const float4*)(g_heb + oidx);
    float4 o4;
    o4.x = qc.x * (ctx.x + hb.x * invn);
    o4.y = qc.y * (ctx.y + hb.y * invn);
    o4.z = qc.z * (ctx.z + hb.z * invn);
    o4.w = qc.w * (ctx.w + hb.w * invn);
    *(float4*)(g_g + oidx) = o4;
}

// ---------------- launch -----------------------------------------------------
extern "C" void kernel_launch(void* const* d_in, const int* in_sizes, int n_in,
                              void* d_out, int out_size)
{
    const float* x           = (const float*)d_in[0];
    const float* enc_q       = (const float*)d_in[1];
    const float* enc_v       = (const float*)d_in[2];
    const float* decoder     = (const float*)d_in[3];
    const float* hebbian     = (const float*)d_in[4];
    const float* m_w1        = (const float*)d_in[5];
    const float* m_b1        = (const float*)d_in[6];
    const float* m_w2        = (const float*)d_in[7];
    const float* m_b2        = (const float*)d_in[8];
    const float* base_metric = (const float*)d_in[9];
    float* out = (float*)d_out;

    cudaFuncSetAttribute(gemm_enc_kernel, cudaFuncAttributeMaxDynamicSharedMemorySize, GEMM_SMEM_BYTES);
    cudaFuncSetAttribute(gemm_dec_kernel, cudaFuncAttributeMaxDynamicSharedMemorySize, GEMM_SMEM_BYTES);
    cudaFuncSetAttribute(gemm_heb_kernel, cudaFuncAttributeMaxDynamicSharedMemorySize, GEMM_SMEM_BYTES);

    gemm_enc_kernel<<<dim3(16, 16), 256, GEMM_SMEM_BYTES>>>(x, enc_q, enc_v);
    mlp1_kernel<<<32, 256>>>(m_w1, m_b1);
    mlp2_kernel<<<32, 256>>>(m_w2, m_b2, base_metric);
    gemm_heb_kernel<<<dim3(8, 16), 256, GEMM_SMEM_BYTES>>>(hebbian);
    window_kernel<<<2048, 256>>>();
    gemm_dec_kernel<<<dim3(8, 16), 256, GEMM_SMEM_BYTES>>>(decoder, out);
}

// round 10
// speedup vs baseline: 2.7126x; 1.0329x over previous
#include <cuda_runtime.h>
#include <math.h>
#include <stdint.h>

// Problem shapes (fixed): B=2, T=1024, D=1024, N=8, HD=128, K=32

// ---------------- scratch (device globals; no allocation allowed) ----------
__device__ float g_qv  [2048u * 2048u];  // rows = b*1024+t, [0,1024)=q, [1024,2048)=v
__device__ float g_sigp[8u * 1024u];     // sig partials: [mt(256-row tiles)][ct*128+c]
__device__ float g_h1p [16u * 1024u];    // mlp1 partials: [dchunk][b*512+j]
__device__ float g_h   [1024];           // [2][512]
__device__ float g_h2p [8u * 2048u];     // mlp2 partials: [ichunk][b*1024+j]
__device__ float g_md  [2048];           // [2][1024]
__device__ float g_heb [2048u * 1024u];  // hebbian context (un-normalized q basis)
__device__ float g_g   [2048u * 1024u];  // q*(context+heb)
__device__ unsigned g_c1 = 0, g_c2 = 0;  // last-block counters (self-resetting)

// ---------------- helpers ----------------------------------------------------
__device__ __forceinline__ uint32_t smem_u32(const void* p) {
    uint32_t a;
    asm("{ .reg .u64 t; cvta.to.shared.u64 t, %1; cvt.u32.u64 %0, t; }" : "=r"(a) : "l"(p));
    return a;
}
__device__ __forceinline__ uint32_t rna_bits(float x) {
    uint32_t u; asm("cvt.rna.tf32.f32 %0, %1;" : "=r"(u) : "f"(x));
    return u;
}
__device__ __forceinline__ void cp16(uint32_t dst, const void* src) {
    asm volatile("cp.async.cg.shared.global [%0], [%1], 16;" :: "r"(dst), "l"(src) : "memory");
}
__device__ __forceinline__ void mma_tf32_16n8k8(float* c, const uint32_t* a, const uint32_t* b) {
    asm volatile(
        "mma.sync.aligned.m16n8k8.row.col.f32.tf32.tf32.f32 "
        "{%0,%1,%2,%3}, {%4,%5,%6,%7}, {%8,%9}, {%0,%1,%2,%3};"
        : "+f"(c[0]), "+f"(c[1]), "+f"(c[2]), "+f"(c[3])
        : "r"(a[0]), "r"(a[1]), "r"(a[2]), "r"(a[3]), "r"(b[0]), "r"(b[1]));
}

// ---------------- tf32 mma.sync GEMM core -----------------------------------
// Block tile (64*MT) x 128, BK=32, 256 threads (8 warps: 4 in M x 2 in N),
// warp tile (16*MT) x 64. A row-major [.,lda], B row-major [K][N] (ldb), raw
// fp32 (RNA-rounded to tf32 at fragment load). Double-buffered cp.async smem.
// sigp != nullptr (enc/q path only): writes the time-weighted column sums of
// this row-tile to sigp[0..127] (non-atomic; one block owns the slot).
#define A_STRIDE 36
#define B_STRIDE 136
#define B_SZ (32 * B_STRIDE)

template<int MT, bool RELU>
__device__ void gemm_mma_core(const float* __restrict__ A, int lda,
                              const float* __restrict__ B, int ldb,
                              float* __restrict__ C, int ldc, int Kdim,
                              float* __restrict__ sigp)
{
    extern __shared__ float smem[];
    constexpr int ROWS = 64 * MT;
    constexpr int ASZ  = ROWS * A_STRIDE;
    constexpr int STG  = ASZ + B_SZ;

    const int tid  = threadIdx.x;
    const int lane = tid & 31;
    const int wid  = tid >> 5;
    const int wm   = wid & 3;          // 0..3 -> (16*MT)-row slab
    const int wn   = wid >> 2;         // 0..1 -> 64-col slab
    const int grp  = lane >> 2;        // 0..7
    const int tig  = lane & 3;         // 0..3

    float acc[MT][8][4];
#pragma unroll
    for (int mt = 0; mt < MT; mt++)
#pragma unroll
        for (int nt = 0; nt < 8; nt++)
#pragma unroll
            for (int q = 0; q < 4; q++) acc[mt][nt][q] = 0.f;

    const int niter = Kdim >> 5;

    auto load_stage = [&](int S, int K0) {
        float* As_ = smem + S * STG;
        float* Bs_ = As_ + ASZ;
#pragma unroll
        for (int it = 0; it < 2 * MT; it++) {
            const int idx = tid + (it << 8);
            const int r_  = idx >> 3, c4_ = idx & 7;
            cp16(smem_u32(As_ + r_ * A_STRIDE + (c4_ << 2)),
                 A + (size_t)r_ * lda + K0 + (c4_ << 2));
        }
#pragma unroll
        for (int it = 0; it < 4; it++) {
            const int idx = tid + (it << 8);
            const int k_ = idx >> 5, n4_ = idx & 31;
            cp16(smem_u32(Bs_ + k_ * B_STRIDE + (n4_ << 2)),
                 B + (size_t)(K0 + k_) * ldb + (n4_ << 2));
        }
        asm volatile("cp.async.commit_group;" ::: "memory");
    };

    load_stage(0, 0);

#pragma unroll 1
    for (int j = 0; j < niter; j++) {
        if (j + 1 < niter) {
            load_stage((j + 1) & 1, (j + 1) << 5);
            asm volatile("cp.async.wait_group 1;" ::: "memory");
        } else {
            asm volatile("cp.async.wait_group 0;" ::: "memory");
        }
        __syncthreads();

        const float* As = smem + (j & 1) * STG;
        const float* Bs = As + ASZ;

#pragma unroll
        for (int kk = 0; kk < 4; kk++) {
            const int kb = kk << 3;
            uint32_t af[MT][4];
#pragma unroll
            for (int mt = 0; mt < MT; mt++) {
                const int r = wm * (16 * MT) + mt * 16 + grp;
                const float* ap = As + r * A_STRIDE + kb + tig;
                af[mt][0] = rna_bits(ap[0]);
                af[mt][1] = rna_bits(ap[8 * A_STRIDE]);
                af[mt][2] = rna_bits(ap[4]);
                af[mt][3] = rna_bits(ap[8 * A_STRIDE + 4]);
            }
            uint32_t bf[8][2];
#pragma unroll
            for (int nt = 0; nt < 8; nt++) {
                const int cc = wn * 64 + nt * 8 + grp;
                const float* bp = Bs + (kb + tig) * B_STRIDE + cc;
                bf[nt][0] = rna_bits(bp[0]);
                bf[nt][1] = rna_bits(bp[4 * B_STRIDE]);
            }
#pragma unroll
            for (int mt = 0; mt < MT; mt++)
#pragma unroll
                for (int nt = 0; nt < 8; nt++)
                    mma_tf32_16n8k8(acc[mt][nt], af[mt], bf[nt]);
        }
        __syncthreads();
    }

    // epilogue (+ optional fused sig accumulation)
    float csum[8][2];
#pragma unroll
    for (int nt = 0; nt < 8; nt++) { csum[nt][0] = 0.f; csum[nt][1] = 0.f; }

#pragma unroll
    for (int mt = 0; mt < MT; mt++) {
        const int r0 = wm * (16 * MT) + mt * 16 + grp;
#pragma unroll
        for (int nt = 0; nt < 8; nt++) {
            const int c0 = wn * 64 + nt * 8 + tig * 2;
            float2 v0 = make_float2(acc[mt][nt][0], acc[mt][nt][1]);
            float2 v1 = make_float2(acc[mt][nt][2], acc[mt][nt][3]);
            if (RELU) {
                v0.x = fmaxf(v0.x, 0.f); v0.y = fmaxf(v0.y, 0.f);
                v1.x = fmaxf(v1.x, 0.f); v1.y = fmaxf(v1.y, 0.f);
            }
            if (sigp) {
                csum[nt][0] += v0.x + v1.x;
                csum[nt][1] += v0.y + v1.y;
            }
            *(float2*)(C + (size_t)r0 * ldc + c0)       = v0;
            *(float2*)(C + (size_t)(r0 + 8) * ldc + c0) = v1;
        }
    }

    if (sigp) {
        // thread's rows are all == grp (mod 8) -> uniform time-weight
        const float w = (1.0f / 1024.0f) + ((grp == 0) ? (0.5f / 128.0f) : 0.f);
        float* sred = smem;      // safe: all threads past final k-loop sync
        if (tid < 128) sred[tid] = 0.f;
        __syncthreads();
#pragma unroll
        for (int nt = 0; nt < 8; nt++) {
            atomicAdd(&sred[wn * 64 + nt * 8 + tig * 2],     w * csum[nt][0]);
            atomicAdd(&sred[wn * 64 + nt * 8 + tig * 2 + 1], w * csum[nt][1]);
        }
        __syncthreads();
        if (tid < 128) sigp[tid] = sred[tid];   // non-atomic: block owns slot
    }
}

#define SMEM_MT2 (2 * (128 * A_STRIDE + B_SZ) * 4)   // 71680 B
#define SMEM_MT4 (2 * (256 * A_STRIDE + B_SZ) * 4)   // 108544 B

// enc: 256x128 tiles (MT=4). grid (16 ct, 8 mt).
__global__ __launch_bounds__(256) void gemm_enc_kernel(
    const float* __restrict__ x, const float* __restrict__ enc_q,
    const float* __restrict__ enc_v)
{
    const int ct = blockIdx.x;   // 0..15: q heads then v heads
    const int mt = blockIdx.y;   // 0..7 (256-row tiles)
    const float* Bp = (ct < 8) ? (enc_q + (size_t)ct * 1024 * 128)
                               : (enc_v + (size_t)(ct - 8) * 1024 * 128);
    float* sigp = (ct < 8) ? (g_sigp + mt * 1024 + ct * 128) : nullptr;
    gemm_mma_core<4, true>(x + (size_t)mt * 256 * 1024, 1024, Bp, 128,
                           g_qv + (size_t)mt * 256 * 2048 + ct * 128, 2048, 1024, sigp);
}
__global__ __launch_bounds__(256) void gemm_dec_kernel(
    const float* __restrict__ dec, float* __restrict__ out)
{
    const int nt = blockIdx.x;   // 0..7
    const int mt = blockIdx.y;   // 0..15
    gemm_mma_core<2, false>(g_g + (size_t)mt * 128 * 1024, 1024,
                            dec + nt * 128, 1024,
                            out + (size_t)mt * 128 * 1024 + nt * 128, 1024, 1024, nullptr);
}
// heb GEMM on RAW q (normalization deferred to window kernel).
__global__ __launch_bounds__(256) void gemm_heb_kernel(const float* __restrict__ heb)
{
    const int n  = blockIdx.x;   // 0..7 head
    const int mt = blockIdx.y;   // 0..15
    gemm_mma_core<2, false>(g_qv + (size_t)mt * 128 * 2048 + n * 128, 2048,
                            heb + (size_t)n * 128 * 128, 128,
                            g_heb + (size_t)mt * 128 * 1024 + n * 128, 1024, 128, nullptr);
}

// ---------------- MLP layer 1: partial GEMM + last-block finish -------------
// grid 32: bid = jb (0..1) | dc<<1 (0..15).  256 threads: one j each, both b.
__global__ void mlp1_kernel(const float* __restrict__ W1, const float* __restrict__ b1)
{
    __shared__ float ssig[2][64];
    __shared__ bool is_last;
    const int tid = threadIdx.x;
    const int jb  = blockIdx.x & 1;
    const int dc  = blockIdx.x >> 1;

    // gather sig chunk: sum 4 tile-partials per (b, d)  (256-row tiles)
    if (tid < 128) {
        const int b = tid >> 6, dl = tid & 63;
        float s = 0.f;
#pragma unroll
        for (int m = 0; m < 4; m++)
            s += g_sigp[(b * 4 + m) * 1024 + dc * 64 + dl];
        ssig[b][dl] = s;
    }
    __syncthreads();

    const int j = jb * 256 + tid;
    float acc0 = 0.f, acc1 = 0.f;
#pragma unroll 8
    for (int dd = 0; dd < 64; dd++) {
        const float w = __ldg(W1 + (size_t)(dc * 64 + dd) * 512 + j);
        acc0 = fmaf(ssig[0][dd], w, acc0);
        acc1 = fmaf(ssig[1][dd], w, acc1);
    }
    g_h1p[dc * 1024 + j]       = acc0;
    g_h1p[dc * 1024 + 512 + j] = acc1;

    __threadfence();
    if (tid == 0) is_last = (atomicAdd(&g_c1, 1u) == 31u);
    __syncthreads();
    if (is_last) {
#pragma unroll
        for (int q = 0; q < 4; q++) {
            const int i = q * 256 + tid;       // 0..1023 = b*512+j
            float a = b1[i & 511];
#pragma unroll
            for (int c = 0; c < 16; c++) a += g_h1p[c * 1024 + i];
            g_h[i] = 0.5f * a * (1.f + erff(a * 0.70710678118654752f));
        }
        __threadfence();
        if (tid == 0) g_c1 = 0u;
    }
}

// ---------------- MLP layer 2: partial GEMM + last-block finish -------------
// grid 32: bid = jb (0..3) | ic<<2 (0..7).  256 threads.
__global__ void mlp2_kernel(const float* __restrict__ W2, const float* __restrict__ b2,
                            const float* __restrict__ base_metric)
{
    __shared__ float sh[2][64];
    __shared__ bool is_last;
    const int tid = threadIdx.x;
    const int jb  = blockIdx.x & 3;
    const int ic  = blockIdx.x >> 2;

    if (tid < 128) {
        const int b = tid >> 6, il = tid & 63;
        sh[b][il] = g_h[b * 512 + ic * 64 + il];
    }
    __syncthreads();

    const int j = jb * 256 + tid;
    float acc0 = 0.f, acc1 = 0.f;
#pragma unroll 8
    for (int ii = 0; ii < 64; ii++) {
        const float w = __ldg(W2 + (size_t)(ic * 64 + ii) * 1024 + j);
        acc0 = fmaf(sh[0][ii], w, acc0);
        acc1 = fmaf(sh[1][ii], w, acc1);
    }
    g_h2p[ic * 2048 + j]        = acc0;
    g_h2p[ic * 2048 + 1024 + j] = acc1;

    __threadfence();
    if (tid == 0) is_last = (atomicAdd(&g_c2, 1u) == 31u);
    __syncthreads();
    if (is_last) {
#pragma unroll
        for (int q = 0; q < 8; q++) {
            const int i = q * 256 + tid;       // 0..2047 = b*1024+j
            const int jj = i & 1023;
            float mod = b2[jj];
#pragma unroll
            for (int c = 0; c < 8; c++) mod += g_h2p[c * 2048 + i];
            const float xv = base_metric[jj] + 0.1f * mod;
            const float sp = fmaxf(xv, 0.f) + log1pf(expf(-fabsf(xv)));
            g_md[i] = sp + 1e-6f;
        }
        __threadfence();
        if (tid == 0) g_c2 = 0u;
    }
}

// ---------------- sliding-window geometric interaction ----------------------
__global__ __launch_bounds__(256) void window_kernel()
{
    __shared__ float buf[8][32][33];
    const int widx = threadIdx.x >> 5;
    const int lane = threadIdx.x & 31;
    const int wg   = blockIdx.x * 8 + widx;
    const int b = wg >> 13;
    const int n = (wg >> 10) & 7;
    const int t = wg & 1023;

    const float* qbase = g_qv + (size_t)b * 1024 * 2048 + n * 128;
    const float* vbase = qbase + 1024;

    const float4 md = *(const float4*)(g_md + b * 1024 + n * 128 + lane * 4);
    const float4 qc = *(const float4*)(qbase + (size_t)t * 2048 + lane * 4);

    float (*mybuf)[33] = buf[widx];

    // phase 1: per-lane partial distances for all 32 window slots
#pragma unroll 1
    for (int k = 0; k < 32; k++) {
        const int row = t - 31 + k;
        float4 w = make_float4(0.f, 0.f, 0.f, 0.f);
        if (row >= 0) w = *(const float4*)(qbase + (size_t)row * 2048 + lane * 4);
        const float dx = qc.x - w.x, dy = qc.y - w.y;
        const float dz = qc.z - w.z, dw = qc.w - w.w;
        mybuf[k][lane] = md.x * dx * dx + md.y * dy * dy + md.z * dz * dz + md.w * dw * dw;
    }
    __syncwarp();

    // transpose-reduce: lane L sums window slot k=L (conflict-free, stride 33)
    float d0 = 0.f, d1 = 0.f, d2 = 0.f, d3 = 0.f;
#pragma unroll
    for (int i = 0; i < 32; i += 4) {
        d0 += mybuf[lane][i];     d1 += mybuf[lane][i + 1];
        d2 += mybuf[lane][i + 2]; d3 += mybuf[lane][i + 3];
    }
    const float e = __expf(-sqrtf((d0 + d1) + (d2 + d3) + 1e-8f));

    float sumw = e;
    float nq = qc.x * qc.x + qc.y * qc.y + qc.z * qc.z + qc.w * qc.w;
#pragma unroll
    for (int o = 16; o > 0; o >>= 1) {
        sumw += __shfl_xor_sync(0xffffffffu, sumw, o);
        nq   += __shfl_xor_sync(0xffffffffu, nq, o);
    }
    const float inv  = 1.f / (sumw + 1e-8f);
    const float invn = 1.f / fmaxf(sqrtf(nq), 1e-12f);

    // phase 2: weighted value aggregation
    float4 ctx = make_float4(0.f, 0.f, 0.f, 0.f);
#pragma unroll 1
    for (int k = 0; k < 32; k++) {
        const int row = t - 31 + k;
        const float wb = __shfl_sync(0xffffffffu, e, k) * inv;
        if (row >= 0) {
            const float4 v = *(const float4*)(vbase + (size_t)row * 2048 + lane * 4);
            ctx.x = fmaf(wb, v.x, ctx.x); ctx.y = fmaf(wb, v.y, ctx.y);
            ctx.z = fmaf(wb, v.z, ctx.z); ctx.w = fmaf(wb, v.w, ctx.w);
        }
    }

    const size_t oidx = (size_t)(b * 1024 + t) * 1024 + n * 128 + lane * 4;
    const float4 hb = *(const float4*)(g_heb + oidx);
    float4 o4;
    o4.x = qc.x * (ctx.x + hb.x * invn);
    o4.y = qc.y * (ctx.y + hb.y * invn);
    o4.z = qc.z * (ctx.z + hb.z * invn);
    o4.w = qc.w * (ctx.w + hb.w * invn);
    *(float4*)(g_g + oidx) = o4;
}

// ---------------- launch -----------------------------------------------------
extern "C" void kernel_launch(void* const* d_in, const int* in_sizes, int n_in,
                              void* d_out, int out_size)
{
    const float* x           = (const float*)d_in[0];
    const float* enc_q       = (const float*)d_in[1];
    const float* enc_v       = (const float*)d_in[2];
    const float* decoder     = (const float*)d_in[3];
    const float* hebbian     = (const float*)d_in[4];
    const float* m_w1        = (const float*)d_in[5];
    const float* m_b1        = (const float*)d_in[6];
    const float* m_w2        = (const float*)d_in[7];
    const float* m_b2        = (const float*)d_in[8];
    const float* base_metric = (const float*)d_in[9];
    float* out = (float*)d_out;

    static cudaStream_t s_side = nullptr;
    static cudaEvent_t ev_enc = nullptr, ev_mlp = nullptr;
    if (!s_side) {
        cudaStreamCreateWithFlags(&s_side, cudaStreamNonBlocking);
        cudaEventCreateWithFlags(&ev_enc, cudaEventDisableTiming);
        cudaEventCreateWithFlags(&ev_mlp, cudaEventDisableTiming);
        cudaFuncSetAttribute(gemm_enc_kernel, cudaFuncAttributeMaxDynamicSharedMemorySize, SMEM_MT4);
        cudaFuncSetAttribute(gemm_dec_kernel, cudaFuncAttributeMaxDynamicSharedMemorySize, SMEM_MT2);
        cudaFuncSetAttribute(gemm_heb_kernel, cudaFuncAttributeMaxDynamicSharedMemorySize, SMEM_MT2);
    }

    gemm_enc_kernel<<<dim3(16, 8), 256, SMEM_MT4>>>(x, enc_q, enc_v);

    // fork: MLP chain on side stream, heb GEMM on main stream (independent)
    cudaEventRecord(ev_enc, 0);
    cudaStreamWaitEvent(s_side, ev_enc, 0);
    mlp1_kernel<<<32, 256, 0, s_side>>>(m_w1, m_b1);
    mlp2_kernel<<<32, 256, 0, s_side>>>(m_w2, m_b2, base_metric);
    cudaEventRecord(ev_mlp, s_side);

    gemm_heb_kernel<<<dim3(8, 16), 256, SMEM_MT2>>>(hebbian);

    // join: window needs g_md (side stream) and g_heb (main stream)
    cudaStreamWaitEvent(0, ev_mlp, 0);
    window_kernel<<<2048, 256>>>();
    gemm_dec_kernel<<<dim3(8, 16), 256, SMEM_MT2>>>(decoder, out);
}